// round 1
// baseline (speedup 1.0000x reference)
#include <cuda_runtime.h>
#include <math.h>

// Problem shape (fixed by the dataset)
#define N_S 8192
#define M_X 4096
#define D_F 784
#define LOG_2PI 1.8378770664093453f

// GEMM tiling
#define BN 128
#define BM 128
#define BK 16
#define MSPLIT 2048   // M is split across blockIdx.y in {0,1}
#define NSPLIT 2

// Scratch (static __device__ arrays; no allocation allowed)
__device__ float g_U[(size_t)N_S * D_F];   // samples / std
__device__ float g_V[(size_t)M_X * D_F];   // x / std
__device__ float g_usq[N_S];               // |u_n|^2
__device__ float g_vsq[M_X];               // |v_m|^2
__device__ float g_c0;                     // -0.5*D*log(2pi) - sum(log std) - log(M)
__device__ float g_pmx[NSPLIT * N_S];      // partial logsumexp max
__device__ float g_ps[NSPLIT * N_S];       // partial logsumexp sum

// ---------------------------------------------------------------------------
// Precompute: one warp per row; u = src/std row-major, plus row sum of u^2.
// WHICH==0 -> g_U/g_usq, WHICH==1 -> g_V/g_vsq
// ---------------------------------------------------------------------------
template <int WHICH>
__global__ void scale_rows_kernel(const float* __restrict__ src,
                                  const float* __restrict__ stdv,
                                  int rows) {
    float* dst = WHICH ? g_V : g_U;
    float* sq  = WHICH ? g_vsq : g_usq;

    int warp = (blockIdx.x * blockDim.x + threadIdx.x) >> 5;
    int lane = threadIdx.x & 31;
    if (warp >= rows) return;

    const float4* s4 = reinterpret_cast<const float4*>(src + (size_t)warp * D_F);
    const float4* t4 = reinterpret_cast<const float4*>(stdv);
    float4* d4       = reinterpret_cast<float4*>(dst + (size_t)warp * D_F);

    float acc = 0.0f;
    for (int q = lane; q < D_F / 4; q += 32) {
        float4 v  = s4[q];
        float4 st = t4[q];
        float4 u;
        u.x = v.x / st.x;
        u.y = v.y / st.y;
        u.z = v.z / st.z;
        u.w = v.w / st.w;
        acc += u.x * u.x + u.y * u.y + u.z * u.z + u.w * u.w;
        d4[q] = u;
    }
#pragma unroll
    for (int o = 16; o > 0; o >>= 1)
        acc += __shfl_xor_sync(0xffffffffu, acc, o);
    if (lane == 0) sq[warp] = acc;
}

// ---------------------------------------------------------------------------
// c0 = -0.5*D*log(2pi) - sum(log std) - log(M)
// ---------------------------------------------------------------------------
__global__ void const_kernel(const float* __restrict__ stdv) {
    __shared__ float red[256];
    int t = threadIdx.x;
    float a = 0.0f;
    for (int d = t; d < D_F; d += 256) a += logf(stdv[d]);
    red[t] = a;
    __syncthreads();
#pragma unroll
    for (int s = 128; s > 0; s >>= 1) {
        if (t < s) red[t] += red[t + s];
        __syncthreads();
    }
    if (t == 0)
        g_c0 = -0.5f * (float)D_F * LOG_2PI - red[0] - logf((float)M_X);
}

// ---------------------------------------------------------------------------
// Main fused kernel: 128x128 tile GEMM (u @ v^T) with online logsumexp over
// the M (column) dimension. Each CTA handles 128 sample rows x 2048 components.
// 256 threads, 8x8 micro-tile per thread.
// ---------------------------------------------------------------------------
__global__ __launch_bounds__(256) void gmm_main_kernel() {
    __shared__ float As[BK][BN + 4];
    __shared__ float Bs[BK][BM + 4];
    __shared__ float red_mx[BN][17];
    __shared__ float red_s[BN][17];

    const int t  = threadIdx.x;
    const int tx = t & 15;   // column group: cols tx*8 .. tx*8+7
    const int ty = t >> 4;   // row group:    rows ty*8 .. ty*8+7
    const int n0 = blockIdx.x * BN;
    const int m_begin = blockIdx.y * MSPLIT;

    float mx[8], sm[8];
#pragma unroll
    for (int i = 0; i < 8; i++) { mx[i] = -INFINITY; sm[i] = 0.0f; }

    for (int mt = 0; mt < MSPLIT; mt += BM) {
        float acc[8][8];
#pragma unroll
        for (int i = 0; i < 8; i++)
#pragma unroll
            for (int j = 0; j < 8; j++) acc[i][j] = 0.0f;

        for (int kt = 0; kt < D_F; kt += BK) {
            __syncthreads();
            // Load A (128x16) and B (128x16) tiles, transposed into smem [k][mn]
#pragma unroll
            for (int i = 0; i < 2; i++) {
                int v   = t + i * 256;        // 0..511
                int row = v >> 2;             // 0..127
                int kq  = (v & 3) * 4;        // 0,4,8,12
                float4 a = *reinterpret_cast<const float4*>(
                    &g_U[(size_t)(n0 + row) * D_F + kt + kq]);
                As[kq + 0][row] = a.x;
                As[kq + 1][row] = a.y;
                As[kq + 2][row] = a.z;
                As[kq + 3][row] = a.w;
                float4 b = *reinterpret_cast<const float4*>(
                    &g_V[(size_t)(m_begin + mt + row) * D_F + kt + kq]);
                Bs[kq + 0][row] = b.x;
                Bs[kq + 1][row] = b.y;
                Bs[kq + 2][row] = b.z;
                Bs[kq + 3][row] = b.w;
            }
            __syncthreads();

#pragma unroll
            for (int kk = 0; kk < BK; kk++) {
                float4 a0 = *reinterpret_cast<float4*>(&As[kk][ty * 8]);
                float4 a1 = *reinterpret_cast<float4*>(&As[kk][ty * 8 + 4]);
                float4 b0 = *reinterpret_cast<float4*>(&Bs[kk][tx * 8]);
                float4 b1 = *reinterpret_cast<float4*>(&Bs[kk][tx * 8 + 4]);
                float av[8] = {a0.x, a0.y, a0.z, a0.w, a1.x, a1.y, a1.z, a1.w};
                float bv[8] = {b0.x, b0.y, b0.z, b0.w, b1.x, b1.y, b1.z, b1.w};
#pragma unroll
                for (int i = 0; i < 8; i++)
#pragma unroll
                    for (int j = 0; j < 8; j++)
                        acc[i][j] = fmaf(av[i], bv[j], acc[i][j]);
            }
        }

        // Epilogue for this 128-column tile: online logsumexp update
        float vs[8];
#pragma unroll
        for (int j = 0; j < 8; j++)
            vs[j] = g_vsq[m_begin + mt + tx * 8 + j];

#pragma unroll
        for (int i = 0; i < 8; i++) {
            float v[8];
            float lm = -INFINITY;
#pragma unroll
            for (int j = 0; j < 8; j++) {
                v[j] = acc[i][j] - 0.5f * vs[j];
                lm = fmaxf(lm, v[j]);
            }
            float ls = 0.0f;
#pragma unroll
            for (int j = 0; j < 8; j++) ls += __expf(v[j] - lm);
            float nm = fmaxf(mx[i], lm);
            sm[i] = sm[i] * __expf(mx[i] - nm) + ls * __expf(lm - nm);
            mx[i] = nm;
        }
    }

    // Cross-thread (16-way) merge per row
#pragma unroll
    for (int i = 0; i < 8; i++) {
        red_mx[ty * 8 + i][tx] = mx[i];
        red_s[ty * 8 + i][tx]  = sm[i];
    }
    __syncthreads();

    if (t < BN) {
        float m = -INFINITY;
#pragma unroll
        for (int j = 0; j < 16; j++) m = fmaxf(m, red_mx[t][j]);
        float s = 0.0f;
#pragma unroll
        for (int j = 0; j < 16; j++)
            s += red_s[t][j] * __expf(red_mx[t][j] - m);
        g_pmx[blockIdx.y * N_S + n0 + t] = m;
        g_ps[blockIdx.y * N_S + n0 + t]  = s;
    }
}

// ---------------------------------------------------------------------------
// Finalize: merge the NSPLIT partials and apply constants.
// ---------------------------------------------------------------------------
__global__ void finalize_kernel(float* __restrict__ out) {
    int n = blockIdx.x * blockDim.x + threadIdx.x;
    if (n >= N_S) return;
    float m0 = g_pmx[n],        s0 = g_ps[n];
    float m1 = g_pmx[N_S + n],  s1 = g_ps[N_S + n];
    float nm = fmaxf(m0, m1);
    float s  = s0 * __expf(m0 - nm) + s1 * __expf(m1 - nm);
    out[n] = g_c0 - 0.5f * g_usq[n] + nm + logf(s);
}

// ---------------------------------------------------------------------------
extern "C" void kernel_launch(void* const* d_in, const int* in_sizes, int n_in,
                              void* d_out, int out_size) {
    const float* samples = (const float*)d_in[0];
    const float* x       = (const float*)d_in[1];
    const float* stdv    = (const float*)d_in[2];
    float* out = (float*)d_out;

    scale_rows_kernel<0><<<N_S / 8, 256>>>(samples, stdv, N_S);
    scale_rows_kernel<1><<<M_X / 8, 256>>>(x, stdv, M_X);
    const_kernel<<<1, 256>>>(stdv);
    gmm_main_kernel<<<dim3(N_S / BN, NSPLIT), 256>>>();
    finalize_kernel<<<(N_S + 255) / 256, 256>>>(out);
}

// round 3
// speedup vs baseline: 5.3337x; 5.3337x over previous
#include <cuda_runtime.h>
#include <cuda_bf16.h>
#include <math.h>
#include <stdint.h>

// ---------------------------------------------------------------- shapes
#define N_S 8192
#define M_X 4096
#define D_F 784
#define D_PAD 832              // 13 * 64, zero padded
#define LOG_2PI 1.8378770664093453f

#define BN 128                 // samples per CTA (MMA M)
#define BM 128                 // components per m-tile (MMA N)
#define MSPLIT 2048
#define NSPLIT 2
#define MTILES (MSPLIT / BM)   // 16
#define KSTAGES (D_PAD / 64)   // 13
#define TOT_STAGES (MTILES * KSTAGES)  // 208
#define NSTAGE 4

#define A_BYTES (BN * 128)     // 16384 (128 rows x 64 bf16)
#define STG_BYTES (2 * A_BYTES)// 32768 (A + B)

// ---------------------------------------------------------------- scratch
__device__ __nv_bfloat16 g_Ubf[(size_t)N_S * D_PAD];
__device__ __nv_bfloat16 g_Vbf[(size_t)M_X * D_PAD];
__device__ float g_usq[N_S];        // |u|^2
__device__ float g_vsqh[M_X];       // 0.5 * |v|^2
__device__ float g_c0;
__device__ float g_pmx[NSPLIT * N_S];
__device__ float g_ps[NSPLIT * N_S];

// ---------------------------------------------------------------- helpers
__device__ __forceinline__ uint32_t smem_u32(const void* p) {
    uint32_t a;
    asm("{ .reg .u64 t; cvta.to.shared.u64 t, %1; cvt.u32.u64 %0, t; }" : "=r"(a) : "l"(p));
    return a;
}
__device__ __forceinline__ void cp_async16(uint32_t dst, const void* src) {
    asm volatile("cp.async.cg.shared.global [%0], [%1], 16;" :: "r"(dst), "l"(src));
}
__device__ __forceinline__ void ldsm_x4(uint32_t* r, uint32_t addr) {
    asm volatile("ldmatrix.sync.aligned.m8n8.x4.shared.b16 {%0,%1,%2,%3}, [%4];"
                 : "=r"(r[0]), "=r"(r[1]), "=r"(r[2]), "=r"(r[3]) : "r"(addr));
}
__device__ __forceinline__ void mma_16816(float* c, const uint32_t* a,
                                          const uint32_t* b) {
    asm volatile(
        "mma.sync.aligned.m16n8k16.row.col.f32.bf16.bf16.f32 "
        "{%0,%1,%2,%3}, {%4,%5,%6,%7}, {%8,%9}, {%0,%1,%2,%3};"
        : "+f"(c[0]), "+f"(c[1]), "+f"(c[2]), "+f"(c[3])
        : "r"(a[0]), "r"(a[1]), "r"(a[2]), "r"(a[3]), "r"(b[0]), "r"(b[1]));
}

// ---------------------------------------------------------------- precompute
template <int WHICH>
__global__ void scale_rows_kernel(const float* __restrict__ src,
                                  const float* __restrict__ stdv, int rows) {
    __nv_bfloat16* dst = WHICH ? g_Vbf : g_Ubf;
    float* sq = WHICH ? g_vsqh : g_usq;

    int warp = (blockIdx.x * blockDim.x + threadIdx.x) >> 5;
    int lane = threadIdx.x & 31;
    if (warp >= rows) return;

    const float4* s4 = reinterpret_cast<const float4*>(src + (size_t)warp * D_F);
    const float4* t4 = reinterpret_cast<const float4*>(stdv);
    __nv_bfloat16* drow = dst + (size_t)warp * D_PAD;

    float acc = 0.0f;
    for (int q = lane; q < D_PAD / 4; q += 32) {
        float4 u = make_float4(0.f, 0.f, 0.f, 0.f);
        if (q < D_F / 4) {
            float4 v = s4[q];
            float4 st = t4[q];
            u.x = v.x / st.x; u.y = v.y / st.y; u.z = v.z / st.z; u.w = v.w / st.w;
            acc += u.x * u.x + u.y * u.y + u.z * u.z + u.w * u.w;
        }
        __nv_bfloat162 p0 = __floats2bfloat162_rn(u.x, u.y);
        __nv_bfloat162 p1 = __floats2bfloat162_rn(u.z, u.w);
        uint2 w;
        w.x = *reinterpret_cast<uint32_t*>(&p0);
        w.y = *reinterpret_cast<uint32_t*>(&p1);
        *reinterpret_cast<uint2*>(drow + q * 4) = w;
    }
#pragma unroll
    for (int o = 16; o > 0; o >>= 1) acc += __shfl_xor_sync(0xffffffffu, acc, o);
    if (lane == 0) sq[warp] = WHICH ? 0.5f * acc : acc;
}

__global__ void const_kernel(const float* __restrict__ stdv) {
    __shared__ float red[256];
    int t = threadIdx.x;
    float a = 0.0f;
    for (int d = t; d < D_F; d += 256) a += logf(stdv[d]);
    red[t] = a;
    __syncthreads();
#pragma unroll
    for (int s = 128; s > 0; s >>= 1) {
        if (t < s) red[t] += red[t + s];
        __syncthreads();
    }
    if (t == 0) g_c0 = -0.5f * (float)D_F * LOG_2PI - red[0] - logf((float)M_X);
}

// ---------------------------------------------------------------- main kernel
// smem layout (within dynamic smem, after 1KB alignment pad):
//   [0, 4*32768)      : pipeline stages (A 16KB + B 16KB each)
//   [131072, +8192)   : vsq (0.5|v|^2 for this split), 2048 floats
//   [139264, +1024)   : red mx (256 floats)
//   [140288, +1024)   : red sm (256 floats)
#define SM_STAGES 0
#define SM_VSQ    (NSTAGE * STG_BYTES)          // 131072
#define SM_REDMX  (SM_VSQ + 8192)
#define SM_REDSM  (SM_REDMX + 1024)
#define SMEM_TOTAL (SM_REDSM + 1024 + 1024)     // +1KB align pad

__device__ __forceinline__ void issue_stage(int g, uint32_t stg0, int tid,
                                            int n0, int m_begin) {
    if (g < TOT_STAGES) {
        int mt = g / KSTAGES;
        int ks = g - mt * KSTAGES;
        uint32_t dstA = stg0 + (g & (NSTAGE - 1)) * STG_BYTES;
        uint32_t dstB = dstA + A_BYTES;
        const char* srcA = (const char*)g_Ubf +
                           ((size_t)n0 * D_PAD + (size_t)ks * 64) * 2;
        const char* srcB = (const char*)g_Vbf +
                           ((size_t)(m_begin + mt * BM) * D_PAD + (size_t)ks * 64) * 2;
#pragma unroll
        for (int i = 0; i < 4; i++) {
            int idx = tid + i * 256;       // 0..1023
            int row = idx >> 3;
            int c   = idx & 7;
            uint32_t sw = (uint32_t)row * 128 + (uint32_t)((c ^ (row & 7)) << 4);
            size_t gsrc = (size_t)row * (D_PAD * 2) + (size_t)c * 16;
            cp_async16(dstA + sw, srcA + gsrc);
            cp_async16(dstB + sw, srcB + gsrc);
        }
    }
    asm volatile("cp.async.commit_group;" ::: "memory");
}

__global__ __launch_bounds__(256, 1) void gmm_hmma_kernel() {
    extern __shared__ char smem_raw[];
    uint32_t sb_raw = smem_u32(smem_raw);
    uint32_t align = (1024u - (sb_raw & 1023u)) & 1023u;
    char* smem = smem_raw + align;
    uint32_t sb = sb_raw + align;
    uint32_t stg0 = sb + SM_STAGES;

    const int tid = threadIdx.x;
    const int lane = tid & 31;
    const int wid = tid >> 5;
    const int warpRow = wid & 3;        // 4 row groups x 32 rows
    const int warpCol = wid >> 2;       // 2 col groups x 64 cols
    const int n0 = blockIdx.x * BN;
    const int m_begin = blockIdx.y * MSPLIT;

    // stage 0.5*|v|^2 into smem
    float* vs = (float*)(smem + SM_VSQ);
    for (int i = tid; i < MSPLIT; i += 256) vs[i] = g_vsqh[m_begin + i];

    // prologue: stages 0..NSTAGE-2
    issue_stage(0, stg0, tid, n0, m_begin);
    issue_stage(1, stg0, tid, n0, m_begin);
    issue_stage(2, stg0, tid, n0, m_begin);

    // ldmatrix lane-address components (constant per thread)
    const int a_rowl = (lane & 7) + ((lane >> 3) & 1) * 8;  // 0..15
    const int a_csel = lane >> 4;                           // 0/1
    const int b_rowl = (lane & 7) + (lane >> 4) * 8;        // 0..15
    const int b_csel = (lane >> 3) & 1;                     // 0/1

    float acc[2][8][4];
#pragma unroll
    for (int rf = 0; rf < 2; rf++)
#pragma unroll
        for (int cf = 0; cf < 8; cf++)
#pragma unroll
            for (int q = 0; q < 4; q++) acc[rf][cf][q] = 0.0f;

    float mx[4], sm[4];
#pragma unroll
    for (int q = 0; q < 4; q++) { mx[q] = -INFINITY; sm[q] = 0.0f; }

    int g = 0;
    for (int mt = 0; mt < MTILES; mt++) {
        for (int ks = 0; ks < KSTAGES; ks++, g++) {
            asm volatile("cp.async.wait_group 2;" ::: "memory");
            __syncthreads();
            issue_stage(g + NSTAGE - 1, stg0, tid, n0, m_begin);

            uint32_t As = stg0 + (g & (NSTAGE - 1)) * STG_BYTES;
            uint32_t Bs = As + A_BYTES;
#pragma unroll
            for (int kk = 0; kk < 4; kk++) {
                uint32_t a[2][4];
#pragma unroll
                for (int rf = 0; rf < 2; rf++) {
                    int r = warpRow * 32 + rf * 16 + a_rowl;
                    int ch = 2 * kk + a_csel;
                    ldsm_x4(a[rf], As + r * 128 + ((ch ^ (r & 7)) << 4));
                }
                uint32_t b[4][4];
#pragma unroll
                for (int cp = 0; cp < 4; cp++) {
                    int r = warpCol * 64 + cp * 16 + b_rowl;
                    int ch = 2 * kk + b_csel;
                    ldsm_x4(b[cp], Bs + r * 128 + ((ch ^ (r & 7)) << 4));
                }
#pragma unroll
                for (int rf = 0; rf < 2; rf++)
#pragma unroll
                    for (int cf = 0; cf < 8; cf++)
                        mma_16816(acc[rf][cf], a[rf], &b[cf >> 1][(cf & 1) * 2]);
            }
        }

        // ---------------- epilogue for this m-tile: online logsumexp
        const float* vsm = vs + mt * BM;
#pragma unroll
        for (int rf = 0; rf < 2; rf++) {
#pragma unroll
            for (int h = 0; h < 2; h++) {
                float v[16];
                float lm = -INFINITY;
#pragma unroll
                for (int cf = 0; cf < 8; cf++) {
                    int col = warpCol * 64 + cf * 8 + (lane & 3) * 2;
                    float v0 = acc[rf][cf][2 * h + 0] - vsm[col];
                    float v1 = acc[rf][cf][2 * h + 1] - vsm[col + 1];
                    v[2 * cf] = v0; v[2 * cf + 1] = v1;
                    lm = fmaxf(lm, fmaxf(v0, v1));
                }
                float ls = 0.f;
#pragma unroll
                for (int j = 0; j < 16; j++) ls += __expf(v[j] - lm);
                // quad reduce across (lane&3) -> full 64-col coverage
#pragma unroll
                for (int o = 1; o <= 2; o <<= 1) {
                    float m2 = __shfl_xor_sync(0xffffffffu, lm, o);
                    float s2 = __shfl_xor_sync(0xffffffffu, ls, o);
                    float nm = fmaxf(lm, m2);
                    ls = ls * __expf(lm - nm) + s2 * __expf(m2 - nm);
                    lm = nm;
                }
                int rs = rf * 2 + h;
                float nm = fmaxf(mx[rs], lm);
                sm[rs] = sm[rs] * __expf(mx[rs] - nm) + ls * __expf(lm - nm);
                mx[rs] = nm;
            }
#pragma unroll
            for (int cf = 0; cf < 8; cf++)
#pragma unroll
                for (int q = 0; q < 4; q++) acc[rf][cf][q] = 0.0f;
        }
    }

    // ---------------- cross-warp merge (2 column halves)
    __syncthreads();
    float* rmx = (float*)(smem + SM_REDMX);
    float* rsm = (float*)(smem + SM_REDSM);
    if ((lane & 3) == 0) {
#pragma unroll
        for (int rf = 0; rf < 2; rf++)
#pragma unroll
            for (int h = 0; h < 2; h++) {
                int rs = rf * 2 + h;
                int row = warpRow * 32 + rf * 16 + h * 8 + (lane >> 2);
                rmx[warpCol * 128 + row] = mx[rs];
                rsm[warpCol * 128 + row] = sm[rs];
            }
    }
    __syncthreads();
    if (tid < 128) {
        float m0 = rmx[tid], s0 = rsm[tid];
        float m1 = rmx[128 + tid], s1 = rsm[128 + tid];
        float nm = fmaxf(m0, m1);
        float s = s0 * __expf(m0 - nm) + s1 * __expf(m1 - nm);
        g_pmx[blockIdx.y * N_S + n0 + tid] = nm;
        g_ps[blockIdx.y * N_S + n0 + tid] = s;
    }
}

// ---------------------------------------------------------------- finalize
__global__ void finalize_kernel(float* __restrict__ out) {
    int n = blockIdx.x * blockDim.x + threadIdx.x;
    if (n >= N_S) return;
    float m0 = g_pmx[n], s0 = g_ps[n];
    float m1 = g_pmx[N_S + n], s1 = g_ps[N_S + n];
    float nm = fmaxf(m0, m1);
    float s = s0 * __expf(m0 - nm) + s1 * __expf(m1 - nm);
    out[n] = g_c0 - g_usq[n] * 0.5f + nm + logf(s);
}

// ---------------------------------------------------------------- launch
extern "C" void kernel_launch(void* const* d_in, const int* in_sizes, int n_in,
                              void* d_out, int out_size) {
    const float* samples = (const float*)d_in[0];
    const float* x       = (const float*)d_in[1];
    const float* stdv    = (const float*)d_in[2];
    float* out = (float*)d_out;

    cudaFuncSetAttribute(gmm_hmma_kernel,
                         cudaFuncAttributeMaxDynamicSharedMemorySize, SMEM_TOTAL);

    scale_rows_kernel<0><<<N_S / 8, 256>>>(samples, stdv, N_S);
    scale_rows_kernel<1><<<M_X / 8, 256>>>(x, stdv, M_X);
    const_kernel<<<1, 256>>>(stdv);
    gmm_hmma_kernel<<<dim3(N_S / BN, NSPLIT), 256, SMEM_TOTAL>>>();
    finalize_kernel<<<(N_S + 255) / 256, 256>>>(out);
}

// round 4
// speedup vs baseline: 9.3090x; 1.7453x over previous
#include <cuda_runtime.h>
#include <cuda_bf16.h>
#include <math.h>
#include <stdint.h>

// ---------------------------------------------------------------- shapes
#define N_S 8192
#define M_X 4096
#define D_F 784
#define D_PAD 832              // 13 * 64, zero padded
#define LOG_2PI 1.8378770664093453f

#define BN 128                 // samples per CTA (MMA M)
#define BM 128                 // components per m-tile (MMA N)
#define MSPLIT 1024
#define NSPLIT 4
#define MTILES (MSPLIT / BM)   // 8
#define KSTAGES (D_PAD / 64)   // 13
#define TOT_STAGES (MTILES * KSTAGES)  // 104
#define NSTAGE 3

#define A_BYTES (BN * 128)     // 16384 (128 rows x 64 bf16)
#define STG_BYTES (2 * A_BYTES)// 32768 (A + B)

// ---------------------------------------------------------------- scratch
__device__ __nv_bfloat16 g_Ubf[(size_t)N_S * D_PAD];
__device__ __nv_bfloat16 g_Vbf[(size_t)M_X * D_PAD];
__device__ float g_usq[N_S];        // |u|^2
__device__ float g_vsqh[M_X];       // 0.5 * |v|^2
__device__ float g_c0;
__device__ float g_pmx[NSPLIT * N_S];
__device__ float g_ps[NSPLIT * N_S];

// ---------------------------------------------------------------- helpers
__device__ __forceinline__ uint32_t smem_u32(const void* p) {
    uint32_t a;
    asm("{ .reg .u64 t; cvta.to.shared.u64 t, %1; cvt.u32.u64 %0, t; }" : "=r"(a) : "l"(p));
    return a;
}
__device__ __forceinline__ void cp_async16(uint32_t dst, const void* src) {
    asm volatile("cp.async.cg.shared.global [%0], [%1], 16;" :: "r"(dst), "l"(src));
}
__device__ __forceinline__ void ldsm_x4(uint32_t* r, uint32_t addr) {
    asm volatile("ldmatrix.sync.aligned.m8n8.x4.shared.b16 {%0,%1,%2,%3}, [%4];"
                 : "=r"(r[0]), "=r"(r[1]), "=r"(r[2]), "=r"(r[3]) : "r"(addr));
}
__device__ __forceinline__ void mma_16816(float* c, const uint32_t* a,
                                          const uint32_t* b) {
    asm volatile(
        "mma.sync.aligned.m16n8k16.row.col.f32.bf16.bf16.f32 "
        "{%0,%1,%2,%3}, {%4,%5,%6,%7}, {%8,%9}, {%0,%1,%2,%3};"
        : "+f"(c[0]), "+f"(c[1]), "+f"(c[2]), "+f"(c[3])
        : "r"(a[0]), "r"(a[1]), "r"(a[2]), "r"(a[3]), "r"(b[0]), "r"(b[1]));
}

// ---------------------------------------------------------------- precompute
template <int WHICH>
__global__ void scale_rows_kernel(const float* __restrict__ src,
                                  const float* __restrict__ stdv, int rows) {
    __nv_bfloat16* dst = WHICH ? g_Vbf : g_Ubf;
    float* sq = WHICH ? g_vsqh : g_usq;

    int warp = (blockIdx.x * blockDim.x + threadIdx.x) >> 5;
    int lane = threadIdx.x & 31;
    if (warp >= rows) return;

    const float4* s4 = reinterpret_cast<const float4*>(src + (size_t)warp * D_F);
    const float4* t4 = reinterpret_cast<const float4*>(stdv);
    __nv_bfloat16* drow = dst + (size_t)warp * D_PAD;

    float acc = 0.0f;
    for (int q = lane; q < D_PAD / 4; q += 32) {
        float4 u = make_float4(0.f, 0.f, 0.f, 0.f);
        if (q < D_F / 4) {
            float4 v = s4[q];
            float4 st = t4[q];
            u.x = v.x / st.x; u.y = v.y / st.y; u.z = v.z / st.z; u.w = v.w / st.w;
            acc += u.x * u.x + u.y * u.y + u.z * u.z + u.w * u.w;
        }
        __nv_bfloat162 p0 = __floats2bfloat162_rn(u.x, u.y);
        __nv_bfloat162 p1 = __floats2bfloat162_rn(u.z, u.w);
        uint2 w;
        w.x = *reinterpret_cast<uint32_t*>(&p0);
        w.y = *reinterpret_cast<uint32_t*>(&p1);
        *reinterpret_cast<uint2*>(drow + q * 4) = w;
    }
#pragma unroll
    for (int o = 16; o > 0; o >>= 1) acc += __shfl_xor_sync(0xffffffffu, acc, o);
    if (lane == 0) sq[warp] = WHICH ? 0.5f * acc : acc;
}

__global__ void const_kernel(const float* __restrict__ stdv) {
    __shared__ float red[256];
    int t = threadIdx.x;
    float a = 0.0f;
    for (int d = t; d < D_F; d += 256) a += logf(stdv[d]);
    red[t] = a;
    __syncthreads();
#pragma unroll
    for (int s = 128; s > 0; s >>= 1) {
        if (t < s) red[t] += red[t + s];
        __syncthreads();
    }
    if (t == 0) g_c0 = -0.5f * (float)D_F * LOG_2PI - red[0] - logf((float)M_X);
}

// ---------------------------------------------------------------- main kernel
// smem layout (after 1KB alignment pad):
//   [0, 3*32768)   : pipeline stages (A 16KB + B 16KB each)
//   [98304, +4096) : vsq (0.5|v|^2 for this split), 1024 floats
//   [+1024]        : red mx (256 floats)
//   [+1024]        : red sm (256 floats)
#define SM_STAGES 0
#define SM_VSQ    (NSTAGE * STG_BYTES)          // 98304
#define SM_REDMX  (SM_VSQ + 4096)
#define SM_REDSM  (SM_REDMX + 1024)
#define SMEM_TOTAL (SM_REDSM + 1024 + 1024)     // ~105KB -> 2 CTAs/SM

__device__ __forceinline__ void issue_stage(int g, uint32_t stg0, int tid,
                                            int n0, int m_begin) {
    if (g < TOT_STAGES) {
        int mt = g / KSTAGES;
        int ks = g - mt * KSTAGES;
        int slot = g % NSTAGE;
        uint32_t dstA = stg0 + slot * STG_BYTES;
        uint32_t dstB = dstA + A_BYTES;
        const char* srcA = (const char*)g_Ubf +
                           ((size_t)n0 * D_PAD + (size_t)ks * 64) * 2;
        const char* srcB = (const char*)g_Vbf +
                           ((size_t)(m_begin + mt * BM) * D_PAD + (size_t)ks * 64) * 2;
#pragma unroll
        for (int i = 0; i < 4; i++) {
            int idx = tid + i * 256;       // 0..1023
            int row = idx >> 3;
            int c   = idx & 7;
            uint32_t sw = (uint32_t)row * 128 + (uint32_t)((c ^ (row & 7)) << 4);
            size_t gsrc = (size_t)row * (D_PAD * 2) + (size_t)c * 16;
            cp_async16(dstA + sw, srcA + gsrc);
            cp_async16(dstB + sw, srcB + gsrc);
        }
    }
    asm volatile("cp.async.commit_group;" ::: "memory");
}

__global__ __launch_bounds__(256, 2) void gmm_hmma_kernel() {
    extern __shared__ char smem_raw[];
    uint32_t sb_raw = smem_u32(smem_raw);
    uint32_t align = (1024u - (sb_raw & 1023u)) & 1023u;
    char* smem = smem_raw + align;
    uint32_t sb = sb_raw + align;
    uint32_t stg0 = sb + SM_STAGES;

    const int tid = threadIdx.x;
    const int lane = tid & 31;
    const int wid = tid >> 5;
    const int warpRow = wid & 3;        // 4 row groups x 32 rows
    const int warpCol = wid >> 2;       // 2 col groups x 64 cols
    const int n0 = blockIdx.x * BN;
    const int m_begin = blockIdx.y * MSPLIT;

    // stage 0.5*|v|^2 into smem
    float* vs = (float*)(smem + SM_VSQ);
    for (int i = tid; i < MSPLIT; i += 256) vs[i] = g_vsqh[m_begin + i];

    // prologue: 2 stages in flight
    issue_stage(0, stg0, tid, n0, m_begin);
    issue_stage(1, stg0, tid, n0, m_begin);

    // ldmatrix lane-address components (constant per thread)
    const int a_rowl = (lane & 7) + ((lane >> 3) & 1) * 8;  // 0..15
    const int a_csel = lane >> 4;                           // 0/1
    const int b_rowl = (lane & 7) + (lane >> 4) * 8;        // 0..15
    const int b_csel = (lane >> 3) & 1;                     // 0/1

    float acc[2][8][4];
#pragma unroll
    for (int rf = 0; rf < 2; rf++)
#pragma unroll
        for (int cf = 0; cf < 8; cf++)
#pragma unroll
            for (int q = 0; q < 4; q++) acc[rf][cf][q] = 0.0f;

    float mx[4], sm[4];
#pragma unroll
    for (int q = 0; q < 4; q++) { mx[q] = -INFINITY; sm[q] = 0.0f; }

    int g = 0;
    for (int mt = 0; mt < MTILES; mt++) {
        for (int ks = 0; ks < KSTAGES; ks++, g++) {
            asm volatile("cp.async.wait_group 1;" ::: "memory");
            __syncthreads();
            issue_stage(g + 2, stg0, tid, n0, m_begin);

            uint32_t As = stg0 + (g % NSTAGE) * STG_BYTES;
            uint32_t Bs = As + A_BYTES;
#pragma unroll
            for (int kk = 0; kk < 4; kk++) {
                uint32_t a[2][4];
#pragma unroll
                for (int rf = 0; rf < 2; rf++) {
                    int r = warpRow * 32 + rf * 16 + a_rowl;
                    int ch = 2 * kk + a_csel;
                    ldsm_x4(a[rf], As + r * 128 + ((ch ^ (r & 7)) << 4));
                }
                uint32_t b[4][4];
#pragma unroll
                for (int cp = 0; cp < 4; cp++) {
                    int r = warpCol * 64 + cp * 16 + b_rowl;
                    int ch = 2 * kk + b_csel;
                    ldsm_x4(b[cp], Bs + r * 128 + ((ch ^ (r & 7)) << 4));
                }
#pragma unroll
                for (int rf = 0; rf < 2; rf++)
#pragma unroll
                    for (int cf = 0; cf < 8; cf++)
                        mma_16816(acc[rf][cf], a[rf], &b[cf >> 1][(cf & 1) * 2]);
            }
        }

        // ---------------- epilogue for this m-tile: online logsumexp
        const float* vsm = vs + mt * BM;
#pragma unroll
        for (int rf = 0; rf < 2; rf++) {
#pragma unroll
            for (int h = 0; h < 2; h++) {
                float v[16];
                float lm = -INFINITY;
#pragma unroll
                for (int cf = 0; cf < 8; cf++) {
                    int col = warpCol * 64 + cf * 8 + (lane & 3) * 2;
                    float v0 = acc[rf][cf][2 * h + 0] - vsm[col];
                    float v1 = acc[rf][cf][2 * h + 1] - vsm[col + 1];
                    v[2 * cf] = v0; v[2 * cf + 1] = v1;
                    lm = fmaxf(lm, fmaxf(v0, v1));
                }
                float ls = 0.f;
#pragma unroll
                for (int j = 0; j < 16; j++) ls += __expf(v[j] - lm);
                // quad reduce across (lane&3) -> full 64-col coverage
#pragma unroll
                for (int o = 1; o <= 2; o <<= 1) {
                    float m2 = __shfl_xor_sync(0xffffffffu, lm, o);
                    float s2 = __shfl_xor_sync(0xffffffffu, ls, o);
                    float nm = fmaxf(lm, m2);
                    ls = ls * __expf(lm - nm) + s2 * __expf(m2 - nm);
                    lm = nm;
                }
                int rs = rf * 2 + h;
                float nm = fmaxf(mx[rs], lm);
                sm[rs] = sm[rs] * __expf(mx[rs] - nm) + ls * __expf(lm - nm);
                mx[rs] = nm;
            }
#pragma unroll
            for (int cf = 0; cf < 8; cf++)
#pragma unroll
                for (int q = 0; q < 4; q++) acc[rf][cf][q] = 0.0f;
        }
    }

    // ---------------- cross-warp merge (2 column halves)
    __syncthreads();
    float* rmx = (float*)(smem + SM_REDMX);
    float* rsm = (float*)(smem + SM_REDSM);
    if ((lane & 3) == 0) {
#pragma unroll
        for (int rf = 0; rf < 2; rf++)
#pragma unroll
            for (int h = 0; h < 2; h++) {
                int rs = rf * 2 + h;
                int row = warpRow * 32 + rf * 16 + h * 8 + (lane >> 2);
                rmx[warpCol * 128 + row] = mx[rs];
                rsm[warpCol * 128 + row] = sm[rs];
            }
    }
    __syncthreads();
    if (tid < 128) {
        float m0 = rmx[tid], s0 = rsm[tid];
        float m1 = rmx[128 + tid], s1 = rsm[128 + tid];
        float nm = fmaxf(m0, m1);
        float s = s0 * __expf(m0 - nm) + s1 * __expf(m1 - nm);
        g_pmx[blockIdx.y * N_S + n0 + tid] = nm;
        g_ps[blockIdx.y * N_S + n0 + tid] = s;
    }
}

// ---------------------------------------------------------------- finalize
__global__ void finalize_kernel(float* __restrict__ out) {
    int n = blockIdx.x * blockDim.x + threadIdx.x;
    if (n >= N_S) return;
    float m = -INFINITY;
#pragma unroll
    for (int p = 0; p < NSPLIT; p++) m = fmaxf(m, g_pmx[p * N_S + n]);
    float s = 0.f;
#pragma unroll
    for (int p = 0; p < NSPLIT; p++)
        s += g_ps[p * N_S + n] * __expf(g_pmx[p * N_S + n] - m);
    out[n] = g_c0 - g_usq[n] * 0.5f + m + logf(s);
}

// ---------------------------------------------------------------- launch
extern "C" void kernel_launch(void* const* d_in, const int* in_sizes, int n_in,
                              void* d_out, int out_size) {
    const float* samples = (const float*)d_in[0];
    const float* x       = (const float*)d_in[1];
    const float* stdv    = (const float*)d_in[2];
    float* out = (float*)d_out;

    cudaFuncSetAttribute(gmm_hmma_kernel,
                         cudaFuncAttributeMaxDynamicSharedMemorySize, SMEM_TOTAL);

    scale_rows_kernel<0><<<N_S / 8, 256>>>(samples, stdv, N_S);
    scale_rows_kernel<1><<<M_X / 8, 256>>>(x, stdv, M_X);
    const_kernel<<<1, 256>>>(stdv);
    gmm_hmma_kernel<<<dim3(N_S / BN, NSPLIT), 256, SMEM_TOTAL>>>();
    finalize_kernel<<<(N_S + 255) / 256, 256>>>(out);
}

// round 5
// speedup vs baseline: 10.4797x; 1.1258x over previous
#include <cuda_runtime.h>
#include <cuda_bf16.h>
#include <math.h>
#include <stdint.h>

// ---------------------------------------------------------------- shapes
#define N_S 8192
#define M_X 4096
#define D_F 784
#define D_PAD 832              // 13 * 64, zero padded
#define LOG_2PI 1.8378770664093453f

#define BN 128                 // samples per unit (MMA M)
#define BM 128                 // components per unit (MMA N)
#define KSTAGES 13             // 13 k-steps of 64 per unit
#define UNITS_N (N_S / BN)     // 64
#define UNITS_M (M_X / BM)     // 32
#define TOT_UNITS (UNITS_N * UNITS_M)   // 2048
#define GRID 296               // 2 CTAs per SM on 148 SMs
#define NSPLIT (UNITS_M * 2)   // 64 partials per sample row
#define NSTAGE 3

#define A_BYTES (BN * 128)     // 16384 (128 rows x 64 bf16)
#define STG_BYTES (2 * A_BYTES)// 32768 (A + B)
#define SMEM_TOTAL (NSTAGE * STG_BYTES + 1024)   // 97.3KB -> 2 CTAs/SM

// ---------------------------------------------------------------- scratch
__device__ __nv_bfloat16 g_Ubf[(size_t)N_S * D_PAD];
__device__ __nv_bfloat16 g_Vbf[(size_t)M_X * D_PAD];
__device__ float g_usq[N_S];        // |u|^2
__device__ float g_vsqh[M_X];       // 0.5 * |v|^2
__device__ float g_c0;
__device__ float g_pmx[NSPLIT * N_S];
__device__ float g_ps[NSPLIT * N_S];

// ---------------------------------------------------------------- helpers
__device__ __forceinline__ uint32_t smem_u32(const void* p) {
    uint32_t a;
    asm("{ .reg .u64 t; cvta.to.shared.u64 t, %1; cvt.u32.u64 %0, t; }" : "=r"(a) : "l"(p));
    return a;
}
__device__ __forceinline__ void cp_async16(uint32_t dst, const void* src) {
    asm volatile("cp.async.cg.shared.global [%0], [%1], 16;" :: "r"(dst), "l"(src));
}
__device__ __forceinline__ void ldsm_x4(uint32_t* r, uint32_t addr) {
    asm volatile("ldmatrix.sync.aligned.m8n8.x4.shared.b16 {%0,%1,%2,%3}, [%4];"
                 : "=r"(r[0]), "=r"(r[1]), "=r"(r[2]), "=r"(r[3]) : "r"(addr));
}
__device__ __forceinline__ void mma_16816(float* c, const uint32_t* a,
                                          const uint32_t* b) {
    asm volatile(
        "mma.sync.aligned.m16n8k16.row.col.f32.bf16.bf16.f32 "
        "{%0,%1,%2,%3}, {%4,%5,%6,%7}, {%8,%9}, {%0,%1,%2,%3};"
        : "+f"(c[0]), "+f"(c[1]), "+f"(c[2]), "+f"(c[3])
        : "r"(a[0]), "r"(a[1]), "r"(a[2]), "r"(a[3]), "r"(b[0]), "r"(b[1]));
}

// ---------------------------------------------------------------- precompute
template <int WHICH>
__global__ void scale_rows_kernel(const float* __restrict__ src,
                                  const float* __restrict__ stdv, int rows) {
    __nv_bfloat16* dst = WHICH ? g_Vbf : g_Ubf;
    float* sq = WHICH ? g_vsqh : g_usq;

    int warp = (blockIdx.x * blockDim.x + threadIdx.x) >> 5;
    int lane = threadIdx.x & 31;
    if (warp >= rows) return;

    const float4* s4 = reinterpret_cast<const float4*>(src + (size_t)warp * D_F);
    const float4* t4 = reinterpret_cast<const float4*>(stdv);
    __nv_bfloat16* drow = dst + (size_t)warp * D_PAD;

    float acc = 0.0f;
    for (int q = lane; q < D_PAD / 4; q += 32) {
        float4 u = make_float4(0.f, 0.f, 0.f, 0.f);
        if (q < D_F / 4) {
            float4 v = s4[q];
            float4 st = t4[q];
            u.x = v.x / st.x; u.y = v.y / st.y; u.z = v.z / st.z; u.w = v.w / st.w;
            acc += u.x * u.x + u.y * u.y + u.z * u.z + u.w * u.w;
        }
        __nv_bfloat162 p0 = __floats2bfloat162_rn(u.x, u.y);
        __nv_bfloat162 p1 = __floats2bfloat162_rn(u.z, u.w);
        uint2 w;
        w.x = *reinterpret_cast<uint32_t*>(&p0);
        w.y = *reinterpret_cast<uint32_t*>(&p1);
        *reinterpret_cast<uint2*>(drow + q * 4) = w;
    }
#pragma unroll
    for (int o = 16; o > 0; o >>= 1) acc += __shfl_xor_sync(0xffffffffu, acc, o);
    if (lane == 0) sq[warp] = WHICH ? 0.5f * acc : acc;
}

__global__ void const_kernel(const float* __restrict__ stdv) {
    __shared__ float red[256];
    int t = threadIdx.x;
    float a = 0.0f;
    for (int d = t; d < D_F; d += 256) a += logf(stdv[d]);
    red[t] = a;
    __syncthreads();
#pragma unroll
    for (int s = 128; s > 0; s >>= 1) {
        if (t < s) red[t] += red[t + s];
        __syncthreads();
    }
    if (t == 0) g_c0 = -0.5f * (float)D_F * LOG_2PI - red[0] - logf((float)M_X);
}

// ---------------------------------------------------------------- main kernel
// Persistent balanced grid: 296 CTAs, unit u = bid + j*296 over 2048 units
// (nt = u>>5, mt = u&31). cp.async pipeline runs continuously across units.
__global__ __launch_bounds__(256, 2) void gmm_hmma_kernel() {
    extern __shared__ char smem_raw[];
    uint32_t sb_raw = smem_u32(smem_raw);
    uint32_t stg0 = (sb_raw + 1023u) & ~1023u;

    const int tid = threadIdx.x;
    const int lane = tid & 31;
    const int wid = tid >> 5;
    const int warpRow = wid & 3;        // 4 row groups x 32 rows
    const int warpCol = wid >> 2;       // 2 col groups x 64 cols
    const int bid = blockIdx.x;

    const int nUnits = (TOT_UNITS - bid + GRID - 1) / GRID;   // 6 or 7
    const int totS = nUnits * KSTAGES;

    // -------- issuer cursor (2 stages ahead of consumer)
    int is_cnt = 0, is_u = bid, is_ks = 0, is_slot = 0;
    auto issue_next = [&]() {
        if (is_cnt < totS) {
            int nt = is_u >> 5, mt = is_u & 31;
            uint32_t dstA = stg0 + is_slot * STG_BYTES;
            uint32_t dstB = dstA + A_BYTES;
            const char* srcA = (const char*)g_Ubf +
                ((size_t)nt * BN * D_PAD + (size_t)is_ks * 64) * 2;
            const char* srcB = (const char*)g_Vbf +
                ((size_t)mt * BM * D_PAD + (size_t)is_ks * 64) * 2;
#pragma unroll
            for (int i = 0; i < 4; i++) {
                int idx = tid + i * 256;       // 0..1023
                int row = idx >> 3;
                int c   = idx & 7;
                uint32_t sw = (uint32_t)row * 128 + (uint32_t)((c ^ (row & 7)) << 4);
                size_t gsrc = (size_t)row * (D_PAD * 2) + (size_t)c * 16;
                cp_async16(dstA + sw, srcA + gsrc);
                cp_async16(dstB + sw, srcB + gsrc);
            }
        }
        asm volatile("cp.async.commit_group;" ::: "memory");
        is_cnt++;
        is_slot = (is_slot == NSTAGE - 1) ? 0 : is_slot + 1;
        if (++is_ks == KSTAGES) { is_ks = 0; is_u += GRID; }
    };

    issue_next();
    issue_next();

    // ldmatrix lane-address components (constant per thread)
    const int a_rowl = (lane & 7) + ((lane >> 3) & 1) * 8;  // 0..15
    const int a_csel = lane >> 4;                           // 0/1
    const int b_rowl = (lane & 7) + (lane >> 4) * 8;        // 0..15
    const int b_csel = (lane >> 3) & 1;                     // 0/1

    int co_slot = 0;
    for (int j = 0; j < nUnits; j++) {
        const int u = bid + j * GRID;
        const int nt = u >> 5, mt = u & 31;
        const int n0 = nt * BN, m0 = mt * BM;

        float acc[2][8][4];
#pragma unroll
        for (int rf = 0; rf < 2; rf++)
#pragma unroll
            for (int cf = 0; cf < 8; cf++)
#pragma unroll
                for (int q = 0; q < 4; q++) acc[rf][cf][q] = 0.0f;

        for (int ks = 0; ks < KSTAGES; ks++) {
            asm volatile("cp.async.wait_group 1;" ::: "memory");
            __syncthreads();
            issue_next();

            uint32_t As = stg0 + co_slot * STG_BYTES;
            uint32_t Bs = As + A_BYTES;
#pragma unroll
            for (int kk = 0; kk < 4; kk++) {
                uint32_t a[2][4];
#pragma unroll
                for (int rf = 0; rf < 2; rf++) {
                    int r = warpRow * 32 + rf * 16 + a_rowl;
                    int ch = 2 * kk + a_csel;
                    ldsm_x4(a[rf], As + r * 128 + ((ch ^ (r & 7)) << 4));
                }
                uint32_t b[4][4];
#pragma unroll
                for (int cp = 0; cp < 4; cp++) {
                    int r = warpCol * 64 + cp * 16 + b_rowl;
                    int ch = 2 * kk + b_csel;
                    ldsm_x4(b[cp], Bs + r * 128 + ((ch ^ (r & 7)) << 4));
                }
#pragma unroll
                for (int rf = 0; rf < 2; rf++)
#pragma unroll
                    for (int cf = 0; cf < 8; cf++)
                        mma_16816(acc[rf][cf], a[rf], &b[cf >> 1][(cf & 1) * 2]);
            }
            co_slot = (co_slot == NSTAGE - 1) ? 0 : co_slot + 1;
        }

        // -------- epilogue: online logsumexp for this 128x128 unit,
        // per-warp quad reduce, direct global partial write (no smem, no sync)
        const float* vsm = g_vsqh + m0 + warpCol * 64;
        float pv[16];
        {
            int cbase = (lane & 3) * 2;
#pragma unroll
            for (int cf = 0; cf < 8; cf++) {
                pv[2 * cf]     = vsm[cf * 8 + cbase];
                pv[2 * cf + 1] = vsm[cf * 8 + cbase + 1];
            }
        }
        const int split = mt * 2 + warpCol;
#pragma unroll
        for (int rf = 0; rf < 2; rf++) {
#pragma unroll
            for (int h = 0; h < 2; h++) {
                float v[16];
                float lm = -INFINITY;
#pragma unroll
                for (int cf = 0; cf < 8; cf++) {
                    float v0 = acc[rf][cf][2 * h + 0] - pv[2 * cf];
                    float v1 = acc[rf][cf][2 * h + 1] - pv[2 * cf + 1];
                    v[2 * cf] = v0; v[2 * cf + 1] = v1;
                    lm = fmaxf(lm, fmaxf(v0, v1));
                }
                float ls = 0.f;
#pragma unroll
                for (int jj = 0; jj < 16; jj++) ls += __expf(v[jj] - lm);
                // quad reduce across (lane&3) -> full 64-col coverage
#pragma unroll
                for (int o = 1; o <= 2; o <<= 1) {
                    float m2 = __shfl_xor_sync(0xffffffffu, lm, o);
                    float s2 = __shfl_xor_sync(0xffffffffu, ls, o);
                    float nm = fmaxf(lm, m2);
                    ls = ls * __expf(lm - nm) + s2 * __expf(m2 - nm);
                    lm = nm;
                }
                if ((lane & 3) == 0) {
                    int row = warpRow * 32 + rf * 16 + h * 8 + (lane >> 2);
                    g_pmx[(size_t)split * N_S + n0 + row] = lm;
                    g_ps[(size_t)split * N_S + n0 + row] = ls;
                }
            }
        }
    }
}

// ---------------------------------------------------------------- finalize
__global__ void finalize_kernel(float* __restrict__ out) {
    int n = blockIdx.x * blockDim.x + threadIdx.x;
    if (n >= N_S) return;
    float m = -INFINITY;
#pragma unroll 8
    for (int p = 0; p < NSPLIT; p++) m = fmaxf(m, g_pmx[p * N_S + n]);
    float s = 0.f;
#pragma unroll 8
    for (int p = 0; p < NSPLIT; p++)
        s += g_ps[p * N_S + n] * __expf(g_pmx[p * N_S + n] - m);
    out[n] = g_c0 - g_usq[n] * 0.5f + m + logf(s);
}

// ---------------------------------------------------------------- launch
extern "C" void kernel_launch(void* const* d_in, const int* in_sizes, int n_in,
                              void* d_out, int out_size) {
    const float* samples = (const float*)d_in[0];
    const float* x       = (const float*)d_in[1];
    const float* stdv    = (const float*)d_in[2];
    float* out = (float*)d_out;

    cudaFuncSetAttribute(gmm_hmma_kernel,
                         cudaFuncAttributeMaxDynamicSharedMemorySize, SMEM_TOTAL);

    scale_rows_kernel<0><<<N_S / 8, 256>>>(samples, stdv, N_S);
    scale_rows_kernel<1><<<M_X / 8, 256>>>(x, stdv, M_X);
    const_kernel<<<1, 256>>>(stdv);
    gmm_hmma_kernel<<<GRID, 256, SMEM_TOTAL>>>();
    finalize_kernel<<<(N_S + 255) / 256, 256>>>(out);
}

// round 6
// speedup vs baseline: 11.1360x; 1.0626x over previous
#include <cuda_runtime.h>
#include <cuda_bf16.h>
#include <math.h>
#include <stdint.h>

// ---------------------------------------------------------------- shapes
#define N_S 8192
#define M_X 4096
#define D_F 784
#define D_PAD 832              // 13 * 64, zero padded
#define LOG_2PI 1.8378770664093453f

#define BN 128                 // samples per unit (MMA M)
#define BM 128                 // components per unit (MMA N)
#define KSTAGES 13             // 13 k-steps of 64 per unit
#define UNITS_N (N_S / BN)     // 64
#define UNITS_M (M_X / BM)     // 32
#define TOT_UNITS (UNITS_N * UNITS_M)   // 2048
#define GRID 296               // 2 CTAs per SM on 148 SMs
#define NSPLIT (UNITS_M * 2)   // 64 partials per sample row
#define NSTAGE 3

#define A_BYTES (BN * 128)     // 16384 (128 rows x 64 bf16)
#define STG_BYTES (2 * A_BYTES)// 32768 (A + B)
#define SMEM_TOTAL (NSTAGE * STG_BYTES + 1024)   // 97.3KB -> 2 CTAs/SM

#define ROWB (D_PAD * 2)       // bytes per row of bf16 matrix (1664)

// ---------------------------------------------------------------- scratch
__device__ __nv_bfloat16 g_Ubf[(size_t)N_S * D_PAD];
__device__ __nv_bfloat16 g_Vbf[(size_t)M_X * D_PAD];
__device__ float g_usq[N_S];        // |u|^2
__device__ float g_vsqh[M_X];       // 0.5 * |v|^2
__device__ float g_c0;
__device__ float2 g_part[(size_t)NSPLIT * N_S];  // (mx, sm) partials

// ---------------------------------------------------------------- helpers
__device__ __forceinline__ uint32_t smem_u32(const void* p) {
    uint32_t a;
    asm("{ .reg .u64 t; cvta.to.shared.u64 t, %1; cvt.u32.u64 %0, t; }" : "=r"(a) : "l"(p));
    return a;
}
__device__ __forceinline__ void cp_async16(uint32_t dst, const void* src) {
    asm volatile("cp.async.cg.shared.global [%0], [%1], 16;" :: "r"(dst), "l"(src));
}
__device__ __forceinline__ void ldsm_x4(uint32_t* r, uint32_t addr) {
    asm volatile("ldmatrix.sync.aligned.m8n8.x4.shared.b16 {%0,%1,%2,%3}, [%4];"
                 : "=r"(r[0]), "=r"(r[1]), "=r"(r[2]), "=r"(r[3]) : "r"(addr));
}
__device__ __forceinline__ void mma_16816(float* c, const uint32_t* a,
                                          const uint32_t* b) {
    asm volatile(
        "mma.sync.aligned.m16n8k16.row.col.f32.bf16.bf16.f32 "
        "{%0,%1,%2,%3}, {%4,%5,%6,%7}, {%8,%9}, {%0,%1,%2,%3};"
        : "+f"(c[0]), "+f"(c[1]), "+f"(c[2]), "+f"(c[3])
        : "r"(a[0]), "r"(a[1]), "r"(a[2]), "r"(a[3]), "r"(b[0]), "r"(b[1]));
}

// ---------------------------------------------------------------- precompute
// Fused: blocks [0, 1536) scale rows of U then V (8 warps/block, 1 row/warp);
// block 1536 computes c0.
#define PRE_BLOCKS ((N_S + M_X) / 8 + 1)
__global__ void precompute_kernel(const float* __restrict__ samples,
                                  const float* __restrict__ x,
                                  const float* __restrict__ stdv) {
    if (blockIdx.x == (N_S + M_X) / 8) {
        __shared__ float red[256];
        int t = threadIdx.x;
        float a = 0.0f;
        for (int d = t; d < D_F; d += 256) a += logf(stdv[d]);
        red[t] = a;
        __syncthreads();
#pragma unroll
        for (int s = 128; s > 0; s >>= 1) {
            if (t < s) red[t] += red[t + s];
            __syncthreads();
        }
        if (t == 0) g_c0 = -0.5f * (float)D_F * LOG_2PI - red[0] - logf((float)M_X);
        return;
    }

    int gw = blockIdx.x * 8 + (threadIdx.x >> 5);   // global warp = row id
    int lane = threadIdx.x & 31;
    bool isV = gw >= N_S;
    int row = isV ? gw - N_S : gw;

    const float* src = isV ? x : samples;
    __nv_bfloat16* dst = isV ? g_Vbf : g_Ubf;
    float* sq = isV ? g_vsqh : g_usq;

    const float4* s4 = reinterpret_cast<const float4*>(src + (size_t)row * D_F);
    const float4* t4 = reinterpret_cast<const float4*>(stdv);
    __nv_bfloat16* drow = dst + (size_t)row * D_PAD;

    float acc = 0.0f;
    for (int q = lane; q < D_PAD / 4; q += 32) {
        float4 u = make_float4(0.f, 0.f, 0.f, 0.f);
        if (q < D_F / 4) {
            float4 v = s4[q];
            float4 st = t4[q];
            u.x = v.x / st.x; u.y = v.y / st.y; u.z = v.z / st.z; u.w = v.w / st.w;
            acc += u.x * u.x + u.y * u.y + u.z * u.z + u.w * u.w;
        }
        __nv_bfloat162 p0 = __floats2bfloat162_rn(u.x, u.y);
        __nv_bfloat162 p1 = __floats2bfloat162_rn(u.z, u.w);
        uint2 w;
        w.x = *reinterpret_cast<uint32_t*>(&p0);
        w.y = *reinterpret_cast<uint32_t*>(&p1);
        *reinterpret_cast<uint2*>(drow + q * 4) = w;
    }
#pragma unroll
    for (int o = 16; o > 0; o >>= 1) acc += __shfl_xor_sync(0xffffffffu, acc, o);
    if (lane == 0) sq[row] = isV ? 0.5f * acc : acc;
}

// ---------------------------------------------------------------- main kernel
// Persistent balanced grid: 296 CTAs, unit u = bid + j*296 over 2048 units
// (nt = u>>5, mt = u&31). cp.async pipeline runs continuously across units.
__global__ __launch_bounds__(256, 2) void gmm_hmma_kernel() {
    extern __shared__ char smem_raw[];
    uint32_t sb_raw = smem_u32(smem_raw);
    uint32_t stg0 = (sb_raw + 1023u) & ~1023u;

    const int tid = threadIdx.x;
    const int lane = tid & 31;
    const int wid = tid >> 5;
    const int warpRow = wid & 3;        // 4 row groups x 32 rows
    const int warpCol = wid >> 2;       // 2 col groups x 64 cols
    const int bid = blockIdx.x;

    const int nUnits = (TOT_UNITS - bid + GRID - 1) / GRID;   // 6 or 7
    const int totS = nUnits * KSTAGES;

    // per-thread constant cp.async offsets (4 chunks of the 1024-chunk tile)
    uint32_t swo[4];      // swizzled smem offsets within a 16KB half-stage
    uint32_t gso[4];      // source byte offsets within a 128-row k-slab
#pragma unroll
    for (int i = 0; i < 4; i++) {
        int idx = tid + i * 256;
        int row = idx >> 3;
        int c   = idx & 7;
        swo[i] = (uint32_t)row * 128 + (uint32_t)((c ^ (row & 7)) << 4);
        gso[i] = (uint32_t)row * ROWB + (uint32_t)c * 16;
    }

    // -------- issuer cursor (2 stages ahead of consumer); incremental pointers
    int is_cnt = 0, is_u = bid, is_ks = 0;
    uint32_t is_dst = stg0;
    const char* pA = (const char*)g_Ubf + (size_t)(bid >> 5) * BN * ROWB;
    const char* pB = (const char*)g_Vbf + (size_t)(bid & 31) * BM * ROWB;

    auto issue_next = [&]() {
        if (is_cnt < totS) {
#pragma unroll
            for (int i = 0; i < 4; i++) {
                cp_async16(is_dst + swo[i], pA + gso[i]);
                cp_async16(is_dst + A_BYTES + swo[i], pB + gso[i]);
            }
        }
        asm volatile("cp.async.commit_group;" ::: "memory");
        is_cnt++;
        is_dst += STG_BYTES;
        if (is_dst == stg0 + NSTAGE * STG_BYTES) is_dst = stg0;
        pA += 128; pB += 128;
        if (++is_ks == KSTAGES) {
            is_ks = 0;
            is_u += GRID;
            pA = (const char*)g_Ubf + (size_t)(is_u >> 5) * BN * ROWB;
            pB = (const char*)g_Vbf + (size_t)(is_u & 31) * BM * ROWB;
        }
    };

    issue_next();
    issue_next();

    // ldmatrix lane-address components (constant per thread)
    const int a_rowl = (lane & 7) + ((lane >> 3) & 1) * 8;  // 0..15
    const int a_csel = lane >> 4;                           // 0/1
    const int b_rowl = (lane & 7) + (lane >> 4) * 8;        // 0..15
    const int b_csel = (lane >> 3) & 1;                     // 0/1

    uint32_t co_base = stg0;
    for (int j = 0; j < nUnits; j++) {
        const int u = bid + j * GRID;
        const int nt = u >> 5, mt = u & 31;
        const int n0 = nt * BN, m0 = mt * BM;

        float acc[2][8][4];
#pragma unroll
        for (int rf = 0; rf < 2; rf++)
#pragma unroll
            for (int cf = 0; cf < 8; cf++)
#pragma unroll
                for (int q = 0; q < 4; q++) acc[rf][cf][q] = 0.0f;

        for (int ks = 0; ks < KSTAGES; ks++) {
            asm volatile("cp.async.wait_group 1;" ::: "memory");
            __syncthreads();
            issue_next();

            uint32_t As = co_base;
            uint32_t Bs = co_base + A_BYTES;
#pragma unroll
            for (int kk = 0; kk < 4; kk++) {
                uint32_t a[2][4];
#pragma unroll
                for (int rf = 0; rf < 2; rf++) {
                    int r = warpRow * 32 + rf * 16 + a_rowl;
                    int ch = 2 * kk + a_csel;
                    ldsm_x4(a[rf], As + r * 128 + ((ch ^ (r & 7)) << 4));
                }
                uint32_t b[4][4];
#pragma unroll
                for (int cp = 0; cp < 4; cp++) {
                    int r = warpCol * 64 + cp * 16 + b_rowl;
                    int ch = 2 * kk + b_csel;
                    ldsm_x4(b[cp], Bs + r * 128 + ((ch ^ (r & 7)) << 4));
                }
#pragma unroll
                for (int rf = 0; rf < 2; rf++)
#pragma unroll
                    for (int cf = 0; cf < 8; cf++)
                        mma_16816(acc[rf][cf], a[rf], &b[cf >> 1][(cf & 1) * 2]);
            }
            co_base += STG_BYTES;
            if (co_base == stg0 + NSTAGE * STG_BYTES) co_base = stg0;
        }

        // -------- epilogue: online logsumexp for this 128x128 unit,
        // per-warp quad reduce, direct global partial write (no smem, no sync)
        const float* vsm = g_vsqh + m0 + warpCol * 64;
        float pv[16];
        {
            int cbase = (lane & 3) * 2;
#pragma unroll
            for (int cf = 0; cf < 8; cf++) {
                pv[2 * cf]     = vsm[cf * 8 + cbase];
                pv[2 * cf + 1] = vsm[cf * 8 + cbase + 1];
            }
        }
        const int split = mt * 2 + warpCol;
#pragma unroll
        for (int rf = 0; rf < 2; rf++) {
#pragma unroll
            for (int h = 0; h < 2; h++) {
                float v[16];
                float lm = -INFINITY;
#pragma unroll
                for (int cf = 0; cf < 8; cf++) {
                    float v0 = acc[rf][cf][2 * h + 0] - pv[2 * cf];
                    float v1 = acc[rf][cf][2 * h + 1] - pv[2 * cf + 1];
                    v[2 * cf] = v0; v[2 * cf + 1] = v1;
                    lm = fmaxf(lm, fmaxf(v0, v1));
                }
                float ls = 0.f;
#pragma unroll
                for (int jj = 0; jj < 16; jj++) ls += __expf(v[jj] - lm);
                // quad reduce across (lane&3) -> full 64-col coverage
#pragma unroll
                for (int o = 1; o <= 2; o <<= 1) {
                    float m2 = __shfl_xor_sync(0xffffffffu, lm, o);
                    float s2 = __shfl_xor_sync(0xffffffffu, ls, o);
                    float nm = fmaxf(lm, m2);
                    ls = ls * __expf(lm - nm) + s2 * __expf(m2 - nm);
                    lm = nm;
                }
                if ((lane & 3) == 0) {
                    int row = warpRow * 32 + rf * 16 + h * 8 + (lane >> 2);
                    g_part[(size_t)split * N_S + n0 + row] = make_float2(lm, ls);
                }
            }
        }
    }
}

// ---------------------------------------------------------------- finalize
__global__ void finalize_kernel(float* __restrict__ out) {
    int n = blockIdx.x * blockDim.x + threadIdx.x;
    if (n >= N_S) return;
    float m = -INFINITY;
    float2 p[NSPLIT / 8][8];
#pragma unroll
    for (int pb = 0; pb < NSPLIT / 8; pb++)
#pragma unroll
        for (int q = 0; q < 8; q++) {
            p[pb][q] = g_part[(size_t)(pb * 8 + q) * N_S + n];
            m = fmaxf(m, p[pb][q].x);
        }
    float s = 0.f;
#pragma unroll
    for (int pb = 0; pb < NSPLIT / 8; pb++)
#pragma unroll
        for (int q = 0; q < 8; q++)
            s += p[pb][q].y * __expf(p[pb][q].x - m);
    out[n] = g_c0 - g_usq[n] * 0.5f + m + logf(s);
}

// ---------------------------------------------------------------- launch
extern "C" void kernel_launch(void* const* d_in, const int* in_sizes, int n_in,
                              void* d_out, int out_size) {
    const float* samples = (const float*)d_in[0];
    const float* x       = (const float*)d_in[1];
    const float* stdv    = (const float*)d_in[2];
    float* out = (float*)d_out;

    cudaFuncSetAttribute(gmm_hmma_kernel,
                         cudaFuncAttributeMaxDynamicSharedMemorySize, SMEM_TOTAL);

    precompute_kernel<<<PRE_BLOCKS, 256>>>(samples, x, stdv);
    gmm_hmma_kernel<<<GRID, 256, SMEM_TOTAL>>>();
    finalize_kernel<<<(N_S + 255) / 256, 256>>>(out);
}

// round 7
// speedup vs baseline: 11.1829x; 1.0042x over previous
#include <cuda_runtime.h>
#include <cuda_bf16.h>
#include <math.h>
#include <stdint.h>

// ---------------------------------------------------------------- shapes
#define N_S 8192
#define M_X 4096
#define D_F 784
#define D_PAD 832              // 13 * 64, zero padded
#define LOG_2PI 1.8378770664093453f

#define BN 128                 // samples per unit (MMA M)
#define BM 128                 // components per unit (MMA N)
#define KSTAGES 13             // 13 k-steps of 64 per unit
#define UNITS_N (N_S / BN)     // 64
#define UNITS_M (M_X / BM)     // 32
#define TOT_UNITS (UNITS_N * UNITS_M)   // 2048
#define GRID 296               // 2 CTAs per SM on 148 SMs
#define NSPLIT (UNITS_M * 2)   // 64 partials per sample row
#define NSTAGE 3

#define A_BYTES (BN * 128)     // 16384 (128 rows x 64 bf16)
#define STG_BYTES (2 * A_BYTES)// 32768 (A + B)
#define SMEM_TOTAL (NSTAGE * STG_BYTES + 1024)   // 97.3KB -> 2 CTAs/SM

#define ROWB (D_PAD * 2)       // bytes per row of bf16 matrix (1664)

// ---------------------------------------------------------------- scratch
__device__ __nv_bfloat16 g_Ubf[(size_t)N_S * D_PAD];
__device__ __nv_bfloat16 g_Vbf[(size_t)M_X * D_PAD];
__device__ float g_usq[N_S];        // |u|^2
__device__ float g_vsqh[M_X];       // 0.5 * |v|^2
__device__ float g_c0;
__device__ float2 g_part[(size_t)NSPLIT * N_S];  // (mx, sm) partials

// ---------------------------------------------------------------- helpers
__device__ __forceinline__ uint32_t smem_u32(const void* p) {
    uint32_t a;
    asm("{ .reg .u64 t; cvta.to.shared.u64 t, %1; cvt.u32.u64 %0, t; }" : "=r"(a) : "l"(p));
    return a;
}
__device__ __forceinline__ void cp_async16(uint32_t dst, const void* src) {
    asm volatile("cp.async.cg.shared.global [%0], [%1], 16;" :: "r"(dst), "l"(src));
}
__device__ __forceinline__ void ldsm_x4(uint32_t* r, uint32_t addr) {
    asm volatile("ldmatrix.sync.aligned.m8n8.x4.shared.b16 {%0,%1,%2,%3}, [%4];"
                 : "=r"(r[0]), "=r"(r[1]), "=r"(r[2]), "=r"(r[3]) : "r"(addr));
}
__device__ __forceinline__ void mma_16816(float* c, const uint32_t* a,
                                          const uint32_t* b) {
    asm volatile(
        "mma.sync.aligned.m16n8k16.row.col.f32.bf16.bf16.f32 "
        "{%0,%1,%2,%3}, {%4,%5,%6,%7}, {%8,%9}, {%0,%1,%2,%3};"
        : "+f"(c[0]), "+f"(c[1]), "+f"(c[2]), "+f"(c[3])
        : "r"(a[0]), "r"(a[1]), "r"(a[2]), "r"(a[3]), "r"(b[0]), "r"(b[1]));
}

// ---------------------------------------------------------------- precompute
// Fused: blocks [0, 1536) scale rows (8 warps/block, 1 row/warp) using a
// block-shared reciprocal table (no per-element division); block 1536
// computes c0.
#define PRE_BLOCKS ((N_S + M_X) / 8 + 1)
__global__ __launch_bounds__(256) void precompute_kernel(
        const float* __restrict__ samples,
        const float* __restrict__ x,
        const float* __restrict__ stdv) {
    if (blockIdx.x == (N_S + M_X) / 8) {
        __shared__ float red[256];
        int t = threadIdx.x;
        float a = 0.0f;
        for (int d = t; d < D_F; d += 256) a += logf(stdv[d]);
        red[t] = a;
        __syncthreads();
#pragma unroll
        for (int s = 128; s > 0; s >>= 1) {
            if (t < s) red[t] += red[t + s];
            __syncthreads();
        }
        if (t == 0) g_c0 = -0.5f * (float)D_F * LOG_2PI - red[0] - logf((float)M_X);
        return;
    }

    __shared__ float rstd[D_PAD];
    {
        int t = threadIdx.x;
        for (int d = t; d < D_PAD; d += 256)
            rstd[d] = (d < D_F) ? 1.0f / stdv[d] : 0.0f;
    }
    __syncthreads();

    int gw = blockIdx.x * 8 + (threadIdx.x >> 5);   // global warp = row id
    int lane = threadIdx.x & 31;
    bool isV = gw >= N_S;
    int row = isV ? gw - N_S : gw;

    const float* src = isV ? x : samples;
    __nv_bfloat16* dst = isV ? g_Vbf : g_Ubf;
    float* sq = isV ? g_vsqh : g_usq;

    const float4* s4 = reinterpret_cast<const float4*>(src + (size_t)row * D_F);
    const float4* r4 = reinterpret_cast<const float4*>(rstd);
    __nv_bfloat16* drow = dst + (size_t)row * D_PAD;

    float acc = 0.0f;
#pragma unroll 4
    for (int q = lane; q < D_PAD / 4; q += 32) {
        float4 u = make_float4(0.f, 0.f, 0.f, 0.f);
        if (q < D_F / 4) {
            float4 v = s4[q];
            float4 rs = r4[q];
            u.x = v.x * rs.x; u.y = v.y * rs.y; u.z = v.z * rs.z; u.w = v.w * rs.w;
            acc += u.x * u.x + u.y * u.y + u.z * u.z + u.w * u.w;
        }
        __nv_bfloat162 p0 = __floats2bfloat162_rn(u.x, u.y);
        __nv_bfloat162 p1 = __floats2bfloat162_rn(u.z, u.w);
        uint2 w;
        w.x = *reinterpret_cast<uint32_t*>(&p0);
        w.y = *reinterpret_cast<uint32_t*>(&p1);
        *reinterpret_cast<uint2*>(drow + q * 4) = w;
    }
#pragma unroll
    for (int o = 16; o > 0; o >>= 1) acc += __shfl_xor_sync(0xffffffffu, acc, o);
    if (lane == 0) sq[row] = isV ? 0.5f * acc : acc;
}

// ---------------------------------------------------------------- main kernel
// Persistent balanced grid: 296 CTAs, unit u = bid + j*296 over 2048 units
// (nt = u>>5, mt = u&31). cp.async pipeline runs continuously across units.
__global__ __launch_bounds__(256, 2) void gmm_hmma_kernel() {
    extern __shared__ char smem_raw[];
    uint32_t sb_raw = smem_u32(smem_raw);
    uint32_t stg0 = (sb_raw + 1023u) & ~1023u;

    const int tid = threadIdx.x;
    const int lane = tid & 31;
    const int wid = tid >> 5;
    const int warpRow = wid & 3;        // 4 row groups x 32 rows
    const int warpCol = wid >> 2;       // 2 col groups x 64 cols
    const int bid = blockIdx.x;

    const int nUnits = (TOT_UNITS - bid + GRID - 1) / GRID;   // 6 or 7
    const int totS = nUnits * KSTAGES;

    // per-thread constant cp.async offsets (4 chunks of the 1024-chunk tile)
    uint32_t swo[4];      // swizzled smem offsets within a 16KB half-stage
    uint32_t gso[4];      // source byte offsets within a 128-row k-slab
#pragma unroll
    for (int i = 0; i < 4; i++) {
        int idx = tid + i * 256;
        int row = idx >> 3;
        int c   = idx & 7;
        swo[i] = (uint32_t)row * 128 + (uint32_t)((c ^ (row & 7)) << 4);
        gso[i] = (uint32_t)row * ROWB + (uint32_t)c * 16;
    }

    // -------- issuer cursor (2 stages ahead of consumer); incremental pointers
    int is_cnt = 0, is_u = bid, is_ks = 0;
    uint32_t is_dst = stg0;
    const char* pA = (const char*)g_Ubf + (size_t)(bid >> 5) * BN * ROWB;
    const char* pB = (const char*)g_Vbf + (size_t)(bid & 31) * BM * ROWB;

    auto issue_next = [&]() {
        if (is_cnt < totS) {
#pragma unroll
            for (int i = 0; i < 4; i++) {
                cp_async16(is_dst + swo[i], pA + gso[i]);
                cp_async16(is_dst + A_BYTES + swo[i], pB + gso[i]);
            }
        }
        asm volatile("cp.async.commit_group;" ::: "memory");
        is_cnt++;
        is_dst += STG_BYTES;
        if (is_dst == stg0 + NSTAGE * STG_BYTES) is_dst = stg0;
        pA += 128; pB += 128;
        if (++is_ks == KSTAGES) {
            is_ks = 0;
            is_u += GRID;
            pA = (const char*)g_Ubf + (size_t)(is_u >> 5) * BN * ROWB;
            pB = (const char*)g_Vbf + (size_t)(is_u & 31) * BM * ROWB;
        }
    };

    issue_next();
    issue_next();

    // ldmatrix lane-address components (constant per thread)
    const int a_rowl = (lane & 7) + ((lane >> 3) & 1) * 8;  // 0..15
    const int a_csel = lane >> 4;                           // 0/1
    const int b_rowl = (lane & 7) + (lane >> 4) * 8;        // 0..15
    const int b_csel = (lane >> 3) & 1;                     // 0/1

    uint32_t co_base = stg0;
    for (int j = 0; j < nUnits; j++) {
        const int u = bid + j * GRID;
        const int nt = u >> 5, mt = u & 31;
        const int n0 = nt * BN, m0 = mt * BM;

        float acc[2][8][4];
#pragma unroll
        for (int rf = 0; rf < 2; rf++)
#pragma unroll
            for (int cf = 0; cf < 8; cf++)
#pragma unroll
                for (int q = 0; q < 4; q++) acc[rf][cf][q] = 0.0f;

        for (int ks = 0; ks < KSTAGES; ks++) {
            asm volatile("cp.async.wait_group 1;" ::: "memory");
            __syncthreads();
            issue_next();

            uint32_t As = co_base;
            uint32_t Bs = co_base + A_BYTES;
#pragma unroll
            for (int kk = 0; kk < 4; kk++) {
                uint32_t a[2][4];
#pragma unroll
                for (int rf = 0; rf < 2; rf++) {
                    int r = warpRow * 32 + rf * 16 + a_rowl;
                    int ch = 2 * kk + a_csel;
                    ldsm_x4(a[rf], As + r * 128 + ((ch ^ (r & 7)) << 4));
                }
                uint32_t b[4][4];
#pragma unroll
                for (int cp = 0; cp < 4; cp++) {
                    int r = warpCol * 64 + cp * 16 + b_rowl;
                    int ch = 2 * kk + b_csel;
                    ldsm_x4(b[cp], Bs + r * 128 + ((ch ^ (r & 7)) << 4));
                }
#pragma unroll
                for (int rf = 0; rf < 2; rf++)
#pragma unroll
                    for (int cf = 0; cf < 8; cf++)
                        mma_16816(acc[rf][cf], a[rf], &b[cf >> 1][(cf & 1) * 2]);
            }
            co_base += STG_BYTES;
            if (co_base == stg0 + NSTAGE * STG_BYTES) co_base = stg0;
        }

        // -------- epilogue: online logsumexp for this 128x128 unit,
        // per-warp quad reduce, direct global partial write (no smem, no sync)
        const float* vsm = g_vsqh + m0 + warpCol * 64;
        float pv[16];
        {
            int cbase = (lane & 3) * 2;
#pragma unroll
            for (int cf = 0; cf < 8; cf++) {
                pv[2 * cf]     = vsm[cf * 8 + cbase];
                pv[2 * cf + 1] = vsm[cf * 8 + cbase + 1];
            }
        }
        const int split = mt * 2 + warpCol;
#pragma unroll
        for (int rf = 0; rf < 2; rf++) {
#pragma unroll
            for (int h = 0; h < 2; h++) {
                float v[16];
                float lm = -INFINITY;
#pragma unroll
                for (int cf = 0; cf < 8; cf++) {
                    float v0 = acc[rf][cf][2 * h + 0] - pv[2 * cf];
                    float v1 = acc[rf][cf][2 * h + 1] - pv[2 * cf + 1];
                    v[2 * cf] = v0; v[2 * cf + 1] = v1;
                    lm = fmaxf(lm, fmaxf(v0, v1));
                }
                float ls = 0.f;
#pragma unroll
                for (int jj = 0; jj < 16; jj++) ls += __expf(v[jj] - lm);
                // quad reduce across (lane&3) -> full 64-col coverage
#pragma unroll
                for (int o = 1; o <= 2; o <<= 1) {
                    float m2 = __shfl_xor_sync(0xffffffffu, lm, o);
                    float s2 = __shfl_xor_sync(0xffffffffu, ls, o);
                    float nm = fmaxf(lm, m2);
                    ls = ls * __expf(lm - nm) + s2 * __expf(m2 - nm);
                    lm = nm;
                }
                if ((lane & 3) == 0) {
                    int row = warpRow * 32 + rf * 16 + h * 8 + (lane >> 2);
                    g_part[(size_t)split * N_S + n0 + row] = make_float2(lm, ls);
                }
            }
        }
    }
}

// ---------------------------------------------------------------- finalize
__global__ void finalize_kernel(float* __restrict__ out) {
    int n = blockIdx.x * blockDim.x + threadIdx.x;
    if (n >= N_S) return;
    float m = -INFINITY;
    float2 p[NSPLIT / 8][8];
#pragma unroll
    for (int pb = 0; pb < NSPLIT / 8; pb++)
#pragma unroll
        for (int q = 0; q < 8; q++) {
            p[pb][q] = g_part[(size_t)(pb * 8 + q) * N_S + n];
            m = fmaxf(m, p[pb][q].x);
        }
    float s = 0.f;
#pragma unroll
    for (int pb = 0; pb < NSPLIT / 8; pb++)
#pragma unroll
        for (int q = 0; q < 8; q++)
            s += p[pb][q].y * __expf(p[pb][q].x - m);
    out[n] = g_c0 - g_usq[n] * 0.5f + m + logf(s);
}

// ---------------------------------------------------------------- launch
extern "C" void kernel_launch(void* const* d_in, const int* in_sizes, int n_in,
                              void* d_out, int out_size) {
    const float* samples = (const float*)d_in[0];
    const float* x       = (const float*)d_in[1];
    const float* stdv    = (const float*)d_in[2];
    float* out = (float*)d_out;

    cudaFuncSetAttribute(gmm_hmma_kernel,
                         cudaFuncAttributeMaxDynamicSharedMemorySize, SMEM_TOTAL);

    precompute_kernel<<<PRE_BLOCKS, 256>>>(samples, x, stdv);
    gmm_hmma_kernel<<<GRID, 256, SMEM_TOTAL>>>();
    finalize_kernel<<<(N_S + 255) / 256, 256>>>(out);
}

// round 8
// speedup vs baseline: 11.2878x; 1.0094x over previous
#include <cuda_runtime.h>
#include <cuda_bf16.h>
#include <math.h>
#include <stdint.h>

// ---------------------------------------------------------------- shapes
#define N_S 8192
#define M_X 4096
#define D_F 784
#define D_PAD 832              // 13 * 64, zero padded
#define LOG_2PI 1.8378770664093453f

#define BN 128                 // samples per unit (MMA M)
#define BM 128                 // components per unit (MMA N)
#define KSTAGES 13             // 13 k-steps of 64 per unit
#define UNITS_N (N_S / BN)     // 64
#define UNITS_M (M_X / BM)     // 32
#define TOT_UNITS (UNITS_N * UNITS_M)   // 2048
#define GRID 296               // 2 CTAs per SM on 148 SMs
#define NSPLIT (UNITS_M * 2)   // 64 partials per sample row
#define NSTAGE 3

#define A_BYTES (BN * 128)     // 16384 (128 rows x 64 bf16)
#define STG_BYTES (2 * A_BYTES)// 32768 (A + B)
#define SMEM_TOTAL (NSTAGE * STG_BYTES + 1024)   // 97.3KB -> 2 CTAs/SM

#define ROWB (D_PAD * 2)       // bytes per row of bf16 matrix (1664)

// ---------------------------------------------------------------- scratch
__device__ __nv_bfloat16 g_Ubf[(size_t)N_S * D_PAD];
__device__ __nv_bfloat16 g_Vbf[(size_t)M_X * D_PAD];
__device__ float g_usq[N_S];        // |u|^2
__device__ float g_vsqh[M_X];       // 0.5 * |v|^2
__device__ float g_c0;
__device__ float2 g_part[(size_t)NSPLIT * N_S];  // (mx, sm) partials

// ---------------------------------------------------------------- helpers
__device__ __forceinline__ uint32_t smem_u32(const void* p) {
    uint32_t a;
    asm("{ .reg .u64 t; cvta.to.shared.u64 t, %1; cvt.u32.u64 %0, t; }" : "=r"(a) : "l"(p));
    return a;
}
__device__ __forceinline__ void cp_async16(uint32_t dst, const void* src) {
    asm volatile("cp.async.cg.shared.global [%0], [%1], 16;" :: "r"(dst), "l"(src));
}
__device__ __forceinline__ void ldsm_x4(uint32_t* r, uint32_t addr) {
    asm volatile("ldmatrix.sync.aligned.m8n8.x4.shared.b16 {%0,%1,%2,%3}, [%4];"
                 : "=r"(r[0]), "=r"(r[1]), "=r"(r[2]), "=r"(r[3]) : "r"(addr));
}
__device__ __forceinline__ void mma_16816(float* c, const uint32_t* a,
                                          const uint32_t* b) {
    asm volatile(
        "mma.sync.aligned.m16n8k16.row.col.f32.bf16.bf16.f32 "
        "{%0,%1,%2,%3}, {%4,%5,%6,%7}, {%8,%9}, {%0,%1,%2,%3};"
        : "+f"(c[0]), "+f"(c[1]), "+f"(c[2]), "+f"(c[3])
        : "r"(a[0]), "r"(a[1]), "r"(a[2]), "r"(a[3]), "r"(b[0]), "r"(b[1]));
}

// ---------------------------------------------------------------- precompute
// Blocks [0, 768): 8 warps, each warp scales TWO adjacent rows (doubled MLP;
// one reciprocal set shared by both rows). Pairing never crosses the U/V
// boundary (8192 is even). Block 768 computes c0.
#define PRE_BLOCKS ((N_S + M_X) / 16 + 1)
__global__ __launch_bounds__(256) void precompute_kernel(
        const float* __restrict__ samples,
        const float* __restrict__ x,
        const float* __restrict__ stdv) {
    if (blockIdx.x == (N_S + M_X) / 16) {
        __shared__ float red[256];
        int t = threadIdx.x;
        float a = 0.0f;
        for (int d = t; d < D_F; d += 256) a += logf(stdv[d]);
        red[t] = a;
        __syncthreads();
#pragma unroll
        for (int s = 128; s > 0; s >>= 1) {
            if (t < s) red[t] += red[t + s];
            __syncthreads();
        }
        if (t == 0) g_c0 = -0.5f * (float)D_F * LOG_2PI - red[0] - logf((float)M_X);
        return;
    }

    int p = blockIdx.x * 8 + (threadIdx.x >> 5);    // row-pair index, 0..6143
    int lane = threadIdx.x & 31;
    bool isV = p >= N_S / 2;
    int row0 = isV ? 2 * p - N_S : 2 * p;

    const float* src = isV ? x : samples;
    __nv_bfloat16* dst = isV ? g_Vbf : g_Ubf;
    float* sq = isV ? g_vsqh : g_usq;

    const float4* s0 = reinterpret_cast<const float4*>(src + (size_t)row0 * D_F);
    const float4* s1 = reinterpret_cast<const float4*>(src + (size_t)(row0 + 1) * D_F);
    const float4* t4 = reinterpret_cast<const float4*>(stdv);
    __nv_bfloat16* d0 = dst + (size_t)row0 * D_PAD;
    __nv_bfloat16* d1 = d0 + D_PAD;

    float acc0 = 0.0f, acc1 = 0.0f;
#pragma unroll 4
    for (int q = lane; q < D_PAD / 4; q += 32) {
        float4 u0 = make_float4(0.f, 0.f, 0.f, 0.f);
        float4 u1 = make_float4(0.f, 0.f, 0.f, 0.f);
        if (q < D_F / 4) {
            float4 v0 = s0[q];
            float4 v1 = s1[q];
            float4 st = t4[q];
            float4 r;
            r.x = 1.0f / st.x; r.y = 1.0f / st.y;
            r.z = 1.0f / st.z; r.w = 1.0f / st.w;
            u0.x = v0.x * r.x; u0.y = v0.y * r.y; u0.z = v0.z * r.z; u0.w = v0.w * r.w;
            u1.x = v1.x * r.x; u1.y = v1.y * r.y; u1.z = v1.z * r.z; u1.w = v1.w * r.w;
            acc0 += u0.x * u0.x + u0.y * u0.y + u0.z * u0.z + u0.w * u0.w;
            acc1 += u1.x * u1.x + u1.y * u1.y + u1.z * u1.z + u1.w * u1.w;
        }
        __nv_bfloat162 a0 = __floats2bfloat162_rn(u0.x, u0.y);
        __nv_bfloat162 a1 = __floats2bfloat162_rn(u0.z, u0.w);
        __nv_bfloat162 b0 = __floats2bfloat162_rn(u1.x, u1.y);
        __nv_bfloat162 b1 = __floats2bfloat162_rn(u1.z, u1.w);
        uint2 w0, w1;
        w0.x = *reinterpret_cast<uint32_t*>(&a0);
        w0.y = *reinterpret_cast<uint32_t*>(&a1);
        w1.x = *reinterpret_cast<uint32_t*>(&b0);
        w1.y = *reinterpret_cast<uint32_t*>(&b1);
        *reinterpret_cast<uint2*>(d0 + q * 4) = w0;
        *reinterpret_cast<uint2*>(d1 + q * 4) = w1;
    }
#pragma unroll
    for (int o = 16; o > 0; o >>= 1) {
        acc0 += __shfl_xor_sync(0xffffffffu, acc0, o);
        acc1 += __shfl_xor_sync(0xffffffffu, acc1, o);
    }
    if (lane == 0) {
        if (isV) {
            sq[row0]     = 0.5f * acc0;
            sq[row0 + 1] = 0.5f * acc1;
        } else {
            sq[row0]     = acc0;
            sq[row0 + 1] = acc1;
        }
    }
}

// ---------------------------------------------------------------- main kernel
// Persistent balanced grid: 296 CTAs, unit u = bid + j*296 over 2048 units
// (nt = u>>5, mt = u&31). cp.async pipeline runs continuously across units.
__global__ __launch_bounds__(256, 2) void gmm_hmma_kernel() {
    extern __shared__ char smem_raw[];
    uint32_t sb_raw = smem_u32(smem_raw);
    uint32_t stg0 = (sb_raw + 1023u) & ~1023u;

    const int tid = threadIdx.x;
    const int lane = tid & 31;
    const int wid = tid >> 5;
    const int warpRow = wid & 3;        // 4 row groups x 32 rows
    const int warpCol = wid >> 2;       // 2 col groups x 64 cols
    const int bid = blockIdx.x;

    const int nUnits = (TOT_UNITS - bid + GRID - 1) / GRID;   // 6 or 7
    const int totS = nUnits * KSTAGES;

    // per-thread constant cp.async offsets (4 chunks of the 1024-chunk tile)
    uint32_t swo[4];      // swizzled smem offsets within a 16KB half-stage
    uint32_t gso[4];      // source byte offsets within a 128-row k-slab
#pragma unroll
    for (int i = 0; i < 4; i++) {
        int idx = tid + i * 256;
        int row = idx >> 3;
        int c   = idx & 7;
        swo[i] = (uint32_t)row * 128 + (uint32_t)((c ^ (row & 7)) << 4);
        gso[i] = (uint32_t)row * ROWB + (uint32_t)c * 16;
    }

    // -------- issuer cursor (2 stages ahead of consumer); incremental pointers
    int is_cnt = 0, is_u = bid, is_ks = 0;
    uint32_t is_dst = stg0;
    const char* pA = (const char*)g_Ubf + (size_t)(bid >> 5) * BN * ROWB;
    const char* pB = (const char*)g_Vbf + (size_t)(bid & 31) * BM * ROWB;

    auto issue_next = [&]() {
        if (is_cnt < totS) {
#pragma unroll
            for (int i = 0; i < 4; i++) {
                cp_async16(is_dst + swo[i], pA + gso[i]);
                cp_async16(is_dst + A_BYTES + swo[i], pB + gso[i]);
            }
        }
        asm volatile("cp.async.commit_group;" ::: "memory");
        is_cnt++;
        is_dst += STG_BYTES;
        if (is_dst == stg0 + NSTAGE * STG_BYTES) is_dst = stg0;
        pA += 128; pB += 128;
        if (++is_ks == KSTAGES) {
            is_ks = 0;
            is_u += GRID;
            pA = (const char*)g_Ubf + (size_t)(is_u >> 5) * BN * ROWB;
            pB = (const char*)g_Vbf + (size_t)(is_u & 31) * BM * ROWB;
        }
    };

    issue_next();
    issue_next();

    // ldmatrix lane-address components (constant per thread)
    const int a_rowl = (lane & 7) + ((lane >> 3) & 1) * 8;  // 0..15
    const int a_csel = lane >> 4;                           // 0/1
    const int b_rowl = (lane & 7) + (lane >> 4) * 8;        // 0..15
    const int b_csel = (lane >> 3) & 1;                     // 0/1

    uint32_t co_base = stg0;
    for (int j = 0; j < nUnits; j++) {
        const int u = bid + j * GRID;
        const int nt = u >> 5, mt = u & 31;
        const int n0 = nt * BN, m0 = mt * BM;

        float acc[2][8][4];
#pragma unroll
        for (int rf = 0; rf < 2; rf++)
#pragma unroll
            for (int cf = 0; cf < 8; cf++)
#pragma unroll
                for (int q = 0; q < 4; q++) acc[rf][cf][q] = 0.0f;

        for (int ks = 0; ks < KSTAGES; ks++) {
            asm volatile("cp.async.wait_group 1;" ::: "memory");
            __syncthreads();
            issue_next();

            uint32_t As = co_base;
            uint32_t Bs = co_base + A_BYTES;
#pragma unroll
            for (int kk = 0; kk < 4; kk++) {
                uint32_t a[2][4];
#pragma unroll
                for (int rf = 0; rf < 2; rf++) {
                    int r = warpRow * 32 + rf * 16 + a_rowl;
                    int ch = 2 * kk + a_csel;
                    ldsm_x4(a[rf], As + r * 128 + ((ch ^ (r & 7)) << 4));
                }
                uint32_t b[4][4];
#pragma unroll
                for (int cp = 0; cp < 4; cp++) {
                    int r = warpCol * 64 + cp * 16 + b_rowl;
                    int ch = 2 * kk + b_csel;
                    ldsm_x4(b[cp], Bs + r * 128 + ((ch ^ (r & 7)) << 4));
                }
#pragma unroll
                for (int rf = 0; rf < 2; rf++)
#pragma unroll
                    for (int cf = 0; cf < 8; cf++)
                        mma_16816(acc[rf][cf], a[rf], &b[cf >> 1][(cf & 1) * 2]);
            }
            co_base += STG_BYTES;
            if (co_base == stg0 + NSTAGE * STG_BYTES) co_base = stg0;
        }

        // -------- epilogue: online logsumexp for this 128x128 unit,
        // per-warp quad reduce, direct global partial write (no smem, no sync)
        const float* vsm = g_vsqh + m0 + warpCol * 64;
        float pv[16];
        {
            int cbase = (lane & 3) * 2;
#pragma unroll
            for (int cf = 0; cf < 8; cf++) {
                pv[2 * cf]     = vsm[cf * 8 + cbase];
                pv[2 * cf + 1] = vsm[cf * 8 + cbase + 1];
            }
        }
        const int split = mt * 2 + warpCol;
#pragma unroll
        for (int rf = 0; rf < 2; rf++) {
#pragma unroll
            for (int h = 0; h < 2; h++) {
                float v[16];
                float lm = -INFINITY;
#pragma unroll
                for (int cf = 0; cf < 8; cf++) {
                    float v0 = acc[rf][cf][2 * h + 0] - pv[2 * cf];
                    float v1 = acc[rf][cf][2 * h + 1] - pv[2 * cf + 1];
                    v[2 * cf] = v0; v[2 * cf + 1] = v1;
                    lm = fmaxf(lm, fmaxf(v0, v1));
                }
                float ls = 0.f;
#pragma unroll
                for (int jj = 0; jj < 16; jj++) ls += __expf(v[jj] - lm);
                // quad reduce across (lane&3) -> full 64-col coverage
#pragma unroll
                for (int o = 1; o <= 2; o <<= 1) {
                    float m2 = __shfl_xor_sync(0xffffffffu, lm, o);
                    float s2 = __shfl_xor_sync(0xffffffffu, ls, o);
                    float nm = fmaxf(lm, m2);
                    ls = ls * __expf(lm - nm) + s2 * __expf(m2 - nm);
                    lm = nm;
                }
                if ((lane & 3) == 0) {
                    int row = warpRow * 32 + rf * 16 + h * 8 + (lane >> 2);
                    g_part[(size_t)split * N_S + n0 + row] = make_float2(lm, ls);
                }
            }
        }
    }
}

// ---------------------------------------------------------------- finalize
__global__ void finalize_kernel(float* __restrict__ out) {
    int n = blockIdx.x * blockDim.x + threadIdx.x;
    if (n >= N_S) return;
    float m = -INFINITY;
    float2 p[NSPLIT / 8][8];
#pragma unroll
    for (int pb = 0; pb < NSPLIT / 8; pb++)
#pragma unroll
        for (int q = 0; q < 8; q++) {
            p[pb][q] = g_part[(size_t)(pb * 8 + q) * N_S + n];
            m = fmaxf(m, p[pb][q].x);
        }
    float s = 0.f;
#pragma unroll
    for (int pb = 0; pb < NSPLIT / 8; pb++)
#pragma unroll
        for (int q = 0; q < 8; q++)
            s += p[pb][q].y * __expf(p[pb][q].x - m);
    out[n] = g_c0 - g_usq[n] * 0.5f + m + logf(s);
}

// ---------------------------------------------------------------- launch
extern "C" void kernel_launch(void* const* d_in, const int* in_sizes, int n_in,
                              void* d_out, int out_size) {
    const float* samples = (const float*)d_in[0];
    const float* x       = (const float*)d_in[1];
    const float* stdv    = (const float*)d_in[2];
    float* out = (float*)d_out;

    cudaFuncSetAttribute(gmm_hmma_kernel,
                         cudaFuncAttributeMaxDynamicSharedMemorySize, SMEM_TOTAL);

    precompute_kernel<<<PRE_BLOCKS, 256>>>(samples, x, stdv);
    gmm_hmma_kernel<<<GRID, 256, SMEM_TOTAL>>>();
    finalize_kernel<<<(N_S + 255) / 256, 256>>>(out);
}

// round 9
// speedup vs baseline: 11.3070x; 1.0017x over previous
#include <cuda_runtime.h>
#include <cuda_bf16.h>
#include <math.h>
#include <stdint.h>

// ---------------------------------------------------------------- shapes
#define N_S 8192
#define M_X 4096
#define D_F 784
#define D_PAD 832              // 13 * 64, zero padded
#define LOG_2PI 1.8378770664093453f

#define BN 128                 // samples per unit (MMA M)
#define BM 128                 // components per unit (MMA N)
#define KSTAGES 13             // 13 k-steps of 64 per unit
#define UNITS_N (N_S / BN)     // 64
#define UNITS_M (M_X / BM)     // 32
#define TOT_UNITS (UNITS_N * UNITS_M)   // 2048
#define GRID 296               // 2 CTAs per SM on 148 SMs
#define NSPLIT (UNITS_M * 2)   // 64 partials per sample row
#define NSTAGE 3

#define A_BYTES (BN * 128)     // 16384 (128 rows x 64 bf16)
#define STG_BYTES (2 * A_BYTES)// 32768 (A + B)
#define SMEM_TOTAL (NSTAGE * STG_BYTES + 1024)   // 97.3KB -> 2 CTAs/SM

#define ROWB (D_PAD * 2)       // bytes per row of bf16 matrix (1664)

// ---------------------------------------------------------------- scratch
__device__ __nv_bfloat16 g_Ubf[(size_t)N_S * D_PAD];
__device__ __nv_bfloat16 g_Vbf[(size_t)M_X * D_PAD];
__device__ float g_usq[N_S];        // |u|^2
__device__ float g_vsqh[M_X];       // 0.5 * |v|^2
__device__ float g_c0;
__device__ float2 g_part[(size_t)NSPLIT * N_S];  // (mx, sm) partials

// ---------------------------------------------------------------- helpers
__device__ __forceinline__ uint32_t smem_u32(const void* p) {
    uint32_t a;
    asm("{ .reg .u64 t; cvta.to.shared.u64 t, %1; cvt.u32.u64 %0, t; }" : "=r"(a) : "l"(p));
    return a;
}
__device__ __forceinline__ void cp_async16(uint32_t dst, const void* src) {
    asm volatile("cp.async.cg.shared.global [%0], [%1], 16;" :: "r"(dst), "l"(src));
}
__device__ __forceinline__ void ldsm_x4(uint32_t* r, uint32_t addr) {
    asm volatile("ldmatrix.sync.aligned.m8n8.x4.shared.b16 {%0,%1,%2,%3}, [%4];"
                 : "=r"(r[0]), "=r"(r[1]), "=r"(r[2]), "=r"(r[3]) : "r"(addr));
}
__device__ __forceinline__ void mma_16816(float* c, const uint32_t* a,
                                          const uint32_t* b) {
    asm volatile(
        "mma.sync.aligned.m16n8k16.row.col.f32.bf16.bf16.f32 "
        "{%0,%1,%2,%3}, {%4,%5,%6,%7}, {%8,%9}, {%0,%1,%2,%3};"
        : "+f"(c[0]), "+f"(c[1]), "+f"(c[2]), "+f"(c[3])
        : "r"(a[0]), "r"(a[1]), "r"(a[2]), "r"(a[3]), "r"(b[0]), "r"(b[1]));
}

// ---------------------------------------------------------------- precompute
// Block = 8 warps = 4 row-pairs; each PAIR is split across 2 warps (one per
// D-half of 104 float4 chunks). Per-lane: 2 independent loads + 2 stores per
// iteration (ILP) AND grid of 1537 blocks (~10/SM, TLP). |u|^2 halves are
// combined via smem. Last block computes c0.
#define PRE_BLOCKS ((N_S + M_X) / 8 + 1)
__global__ __launch_bounds__(256) void precompute_kernel(
        const float* __restrict__ samples,
        const float* __restrict__ x,
        const float* __restrict__ stdv) {
    if (blockIdx.x == (N_S + M_X) / 8) {
        __shared__ float red[256];
        int t = threadIdx.x;
        float a = 0.0f;
        for (int d = t; d < D_F; d += 256) a += logf(stdv[d]);
        red[t] = a;
        __syncthreads();
#pragma unroll
        for (int s = 128; s > 0; s >>= 1) {
            if (t < s) red[t] += red[t + s];
            __syncthreads();
        }
        if (t == 0) g_c0 = -0.5f * (float)D_F * LOG_2PI - red[0] - logf((float)M_X);
        return;
    }

    __shared__ float pacc[4][2][2];     // [pair-in-block][row-in-pair][half]

    const int w = threadIdx.x >> 5;
    const int lane = threadIdx.x & 31;
    const int pairb = w >> 1;           // 0..3
    const int half = w & 1;             // D-half

    const int p = blockIdx.x * 4 + pairb;   // global row-pair, 0..6143
    const bool isV = p >= N_S / 2;
    const int row0 = isV ? 2 * p - N_S : 2 * p;

    const float* src = isV ? x : samples;
    __nv_bfloat16* dst = isV ? g_Vbf : g_Ubf;

    const float4* s0 = reinterpret_cast<const float4*>(src + (size_t)row0 * D_F);
    const float4* s1 = reinterpret_cast<const float4*>(src + (size_t)(row0 + 1) * D_F);
    const float4* t4 = reinterpret_cast<const float4*>(stdv);
    __nv_bfloat16* d0 = dst + (size_t)row0 * D_PAD;
    __nv_bfloat16* d1 = d0 + D_PAD;

    const int qbase = half * (D_PAD / 8);   // 0 or 104

    float acc0 = 0.0f, acc1 = 0.0f;
#pragma unroll
    for (int qq = lane; qq < D_PAD / 8; qq += 32) {
        int q = qbase + qq;
        float4 u0 = make_float4(0.f, 0.f, 0.f, 0.f);
        float4 u1 = make_float4(0.f, 0.f, 0.f, 0.f);
        if (q < D_F / 4) {
            float4 v0 = s0[q];
            float4 v1 = s1[q];
            float4 st = t4[q];
            float4 r;
            r.x = 1.0f / st.x; r.y = 1.0f / st.y;
            r.z = 1.0f / st.z; r.w = 1.0f / st.w;
            u0.x = v0.x * r.x; u0.y = v0.y * r.y; u0.z = v0.z * r.z; u0.w = v0.w * r.w;
            u1.x = v1.x * r.x; u1.y = v1.y * r.y; u1.z = v1.z * r.z; u1.w = v1.w * r.w;
            acc0 += u0.x * u0.x + u0.y * u0.y + u0.z * u0.z + u0.w * u0.w;
            acc1 += u1.x * u1.x + u1.y * u1.y + u1.z * u1.z + u1.w * u1.w;
        }
        __nv_bfloat162 a0 = __floats2bfloat162_rn(u0.x, u0.y);
        __nv_bfloat162 a1 = __floats2bfloat162_rn(u0.z, u0.w);
        __nv_bfloat162 b0 = __floats2bfloat162_rn(u1.x, u1.y);
        __nv_bfloat162 b1 = __floats2bfloat162_rn(u1.z, u1.w);
        uint2 w0, w1;
        w0.x = *reinterpret_cast<uint32_t*>(&a0);
        w0.y = *reinterpret_cast<uint32_t*>(&a1);
        w1.x = *reinterpret_cast<uint32_t*>(&b0);
        w1.y = *reinterpret_cast<uint32_t*>(&b1);
        *reinterpret_cast<uint2*>(d0 + q * 4) = w0;
        *reinterpret_cast<uint2*>(d1 + q * 4) = w1;
    }
#pragma unroll
    for (int o = 16; o > 0; o >>= 1) {
        acc0 += __shfl_xor_sync(0xffffffffu, acc0, o);
        acc1 += __shfl_xor_sync(0xffffffffu, acc1, o);
    }
    if (lane == 0) {
        pacc[pairb][0][half] = acc0;
        pacc[pairb][1][half] = acc1;
    }
    __syncthreads();
    if (threadIdx.x < 8) {
        int pb = threadIdx.x >> 1, r = threadIdx.x & 1;
        int pp = blockIdx.x * 4 + pb;
        bool iV = pp >= N_S / 2;
        int rr = (iV ? 2 * pp - N_S : 2 * pp) + r;
        float a = pacc[pb][r][0] + pacc[pb][r][1];
        if (iV) g_vsqh[rr] = 0.5f * a;
        else    g_usq[rr] = a;
    }
}

// ---------------------------------------------------------------- main kernel
// Persistent balanced grid: 296 CTAs, unit u = bid + j*296 over 2048 units
// (nt = u>>5, mt = u&31). cp.async pipeline runs continuously across units.
__global__ __launch_bounds__(256, 2) void gmm_hmma_kernel() {
    extern __shared__ char smem_raw[];
    uint32_t sb_raw = smem_u32(smem_raw);
    uint32_t stg0 = (sb_raw + 1023u) & ~1023u;

    const int tid = threadIdx.x;
    const int lane = tid & 31;
    const int wid = tid >> 5;
    const int warpRow = wid & 3;        // 4 row groups x 32 rows
    const int warpCol = wid >> 2;       // 2 col groups x 64 cols
    const int bid = blockIdx.x;

    const int nUnits = (TOT_UNITS - bid + GRID - 1) / GRID;   // 6 or 7
    const int totS = nUnits * KSTAGES;

    // per-thread constant cp.async offsets (4 chunks of the 1024-chunk tile)
    uint32_t swo[4];      // swizzled smem offsets within a 16KB half-stage
    uint32_t gso[4];      // source byte offsets within a 128-row k-slab
#pragma unroll
    for (int i = 0; i < 4; i++) {
        int idx = tid + i * 256;
        int row = idx >> 3;
        int c   = idx & 7;
        swo[i] = (uint32_t)row * 128 + (uint32_t)((c ^ (row & 7)) << 4);
        gso[i] = (uint32_t)row * ROWB + (uint32_t)c * 16;
    }

    // -------- issuer cursor (2 stages ahead of consumer); incremental pointers
    int is_cnt = 0, is_u = bid, is_ks = 0;
    uint32_t is_dst = stg0;
    const char* pA = (const char*)g_Ubf + (size_t)(bid >> 5) * BN * ROWB;
    const char* pB = (const char*)g_Vbf + (size_t)(bid & 31) * BM * ROWB;

    auto issue_next = [&]() {
        if (is_cnt < totS) {
#pragma unroll
            for (int i = 0; i < 4; i++) {
                cp_async16(is_dst + swo[i], pA + gso[i]);
                cp_async16(is_dst + A_BYTES + swo[i], pB + gso[i]);
            }
        }
        asm volatile("cp.async.commit_group;" ::: "memory");
        is_cnt++;
        is_dst += STG_BYTES;
        if (is_dst == stg0 + NSTAGE * STG_BYTES) is_dst = stg0;
        pA += 128; pB += 128;
        if (++is_ks == KSTAGES) {
            is_ks = 0;
            is_u += GRID;
            pA = (const char*)g_Ubf + (size_t)(is_u >> 5) * BN * ROWB;
            pB = (const char*)g_Vbf + (size_t)(is_u & 31) * BM * ROWB;
        }
    };

    issue_next();
    issue_next();

    // ldmatrix lane-address components (constant per thread)
    const int a_rowl = (lane & 7) + ((lane >> 3) & 1) * 8;  // 0..15
    const int a_csel = lane >> 4;                           // 0/1
    const int b_rowl = (lane & 7) + (lane >> 4) * 8;        // 0..15
    const int b_csel = (lane >> 3) & 1;                     // 0/1

    uint32_t co_base = stg0;
    for (int j = 0; j < nUnits; j++) {
        const int u = bid + j * GRID;
        const int nt = u >> 5, mt = u & 31;
        const int n0 = nt * BN, m0 = mt * BM;

        float acc[2][8][4];
#pragma unroll
        for (int rf = 0; rf < 2; rf++)
#pragma unroll
            for (int cf = 0; cf < 8; cf++)
#pragma unroll
                for (int q = 0; q < 4; q++) acc[rf][cf][q] = 0.0f;

        for (int ks = 0; ks < KSTAGES; ks++) {
            asm volatile("cp.async.wait_group 1;" ::: "memory");
            __syncthreads();
            issue_next();

            uint32_t As = co_base;
            uint32_t Bs = co_base + A_BYTES;
#pragma unroll
            for (int kk = 0; kk < 4; kk++) {
                uint32_t a[2][4];
#pragma unroll
                for (int rf = 0; rf < 2; rf++) {
                    int r = warpRow * 32 + rf * 16 + a_rowl;
                    int ch = 2 * kk + a_csel;
                    ldsm_x4(a[rf], As + r * 128 + ((ch ^ (r & 7)) << 4));
                }
                uint32_t b[4][4];
#pragma unroll
                for (int cp = 0; cp < 4; cp++) {
                    int r = warpCol * 64 + cp * 16 + b_rowl;
                    int ch = 2 * kk + b_csel;
                    ldsm_x4(b[cp], Bs + r * 128 + ((ch ^ (r & 7)) << 4));
                }
#pragma unroll
                for (int rf = 0; rf < 2; rf++)
#pragma unroll
                    for (int cf = 0; cf < 8; cf++)
                        mma_16816(acc[rf][cf], a[rf], &b[cf >> 1][(cf & 1) * 2]);
            }
            co_base += STG_BYTES;
            if (co_base == stg0 + NSTAGE * STG_BYTES) co_base = stg0;
        }

        // -------- epilogue: online logsumexp for this 128x128 unit,
        // per-warp quad reduce, direct global partial write (no smem, no sync)
        const float* vsm = g_vsqh + m0 + warpCol * 64;
        float pv[16];
        {
            int cbase = (lane & 3) * 2;
#pragma unroll
            for (int cf = 0; cf < 8; cf++) {
                pv[2 * cf]     = vsm[cf * 8 + cbase];
                pv[2 * cf + 1] = vsm[cf * 8 + cbase + 1];
            }
        }
        const int split = mt * 2 + warpCol;
#pragma unroll
        for (int rf = 0; rf < 2; rf++) {
#pragma unroll
            for (int h = 0; h < 2; h++) {
                float v[16];
                float lm = -INFINITY;
#pragma unroll
                for (int cf = 0; cf < 8; cf++) {
                    float v0 = acc[rf][cf][2 * h + 0] - pv[2 * cf];
                    float v1 = acc[rf][cf][2 * h + 1] - pv[2 * cf + 1];
                    v[2 * cf] = v0; v[2 * cf + 1] = v1;
                    lm = fmaxf(lm, fmaxf(v0, v1));
                }
                float ls = 0.f;
#pragma unroll
                for (int jj = 0; jj < 16; jj++) ls += __expf(v[jj] - lm);
                // quad reduce across (lane&3) -> full 64-col coverage
#pragma unroll
                for (int o = 1; o <= 2; o <<= 1) {
                    float m2 = __shfl_xor_sync(0xffffffffu, lm, o);
                    float s2 = __shfl_xor_sync(0xffffffffu, ls, o);
                    float nm = fmaxf(lm, m2);
                    ls = ls * __expf(lm - nm) + s2 * __expf(m2 - nm);
                    lm = nm;
                }
                if ((lane & 3) == 0) {
                    int row = warpRow * 32 + rf * 16 + h * 8 + (lane >> 2);
                    g_part[(size_t)split * N_S + n0 + row] = make_float2(lm, ls);
                }
            }
        }
    }
}

// ---------------------------------------------------------------- finalize
__global__ void finalize_kernel(float* __restrict__ out) {
    int n = blockIdx.x * blockDim.x + threadIdx.x;
    if (n >= N_S) return;
    float m = -INFINITY;
    float2 p[NSPLIT / 8][8];
#pragma unroll
    for (int pb = 0; pb < NSPLIT / 8; pb++)
#pragma unroll
        for (int q = 0; q < 8; q++) {
            p[pb][q] = g_part[(size_t)(pb * 8 + q) * N_S + n];
            m = fmaxf(m, p[pb][q].x);
        }
    float s = 0.f;
#pragma unroll
    for (int pb = 0; pb < NSPLIT / 8; pb++)
#pragma unroll
        for (int q = 0; q < 8; q++)
            s += p[pb][q].y * __expf(p[pb][q].x - m);
    out[n] = g_c0 - g_usq[n] * 0.5f + m + logf(s);
}

// ---------------------------------------------------------------- launch
extern "C" void kernel_launch(void* const* d_in, const int* in_sizes, int n_in,
                              void* d_out, int out_size) {
    const float* samples = (const float*)d_in[0];
    const float* x       = (const float*)d_in[1];
    const float* stdv    = (const float*)d_in[2];
    float* out = (float*)d_out;

    cudaFuncSetAttribute(gmm_hmma_kernel,
                         cudaFuncAttributeMaxDynamicSharedMemorySize, SMEM_TOTAL);

    precompute_kernel<<<PRE_BLOCKS, 256>>>(samples, x, stdv);
    gmm_hmma_kernel<<<GRID, 256, SMEM_TOTAL>>>();
    finalize_kernel<<<(N_S + 255) / 256, 256>>>(out);
}